// round 6
// baseline (speedup 1.0000x reference)
#include <cuda_runtime.h>
#include <cuda_bf16.h>
#include <cfloat>
#include <cstdint>
#include <cstddef>

#define B_  2
#define T_  16
#define NP  1024
#define KNN 16
#define TOUT 14
#define C0 6
#define C1 64
#define C2 128
#define C3 256
#define EPSV 1e-5f

#define P1 (B_*T_*NP*KNN)
#define PM (B_*T_*NP)
#define PT (B_*TOUT*NP)

// ---------------- scratch ----------------
__device__ float g_feats[(size_t)P1*C0];
__device__ float g_h0[(size_t)P1*C1];
__device__ float g_h1[(size_t)P1*C2];
__device__ float g_xm[(size_t)PM*C3];
__device__ float g_y[(size_t)PT*C3];
__device__ float g_pA[(P1/128)*C3];
__device__ float g_pB[(P1/128)*C3];
__device__ float g_scale[4*256];
__device__ float g_shift[4*256];
// pre-split, pre-swizzled bf16 weights: per chunk [hi N*64][lo N*64]
__device__ __nv_bfloat16 g_w1x[1*2*128*64];
__device__ __nv_bfloat16 g_w2x[2*2*256*64];
__device__ __nv_bfloat16 g_wtx[12*2*256*64];
// pre-converted split-bf16 activations, tiled (128 rows x 64 cols, swizzled, hi+lo)
__device__ __nv_bfloat16 g_h0x[(size_t)P1*C1*2];
__device__ __nv_bfloat16 g_h1x[(size_t)P1*C2*2];
__device__ __nv_bfloat16 g_xmx[(size_t)PM*C3*2];

#define SWZ(x) ((x) ^ (((x) >> 3) & 0x70))

__device__ __forceinline__ uint32_t smem_u32(const void* p) {
    uint32_t a;
    asm("{ .reg .u64 t; cvta.to.shared.u64 t, %1; cvt.u32.u64 %0, t; }" : "=r"(a) : "l"(p));
    return a;
}
__device__ __forceinline__ uint32_t pkbf(float a, float b) {
    __nv_bfloat162 h = __floats2bfloat162_rn(a, b);
    return *reinterpret_cast<uint32_t*>(&h);
}
__device__ __forceinline__ void ldm_x4(uint32_t addr, uint32_t& r0, uint32_t& r1,
                                       uint32_t& r2, uint32_t& r3) {
    asm volatile("ldmatrix.sync.aligned.m8n8.x4.shared.b16 {%0,%1,%2,%3}, [%4];"
                 : "=r"(r0), "=r"(r1), "=r"(r2), "=r"(r3) : "r"(addr));
}
__device__ __forceinline__ void mma16816(float* d, const uint32_t* a, const uint32_t* b) {
    asm volatile("mma.sync.aligned.m16n8k16.row.col.f32.bf16.bf16.f32 "
        "{%0,%1,%2,%3}, {%4,%5,%6,%7}, {%8,%9}, {%0,%1,%2,%3};"
        : "+f"(d[0]), "+f"(d[1]), "+f"(d[2]), "+f"(d[3])
        : "r"(a[0]), "r"(a[1]), "r"(a[2]), "r"(a[3]), "r"(b[0]), "r"(b[1]));
}
__device__ __forceinline__ void cpasync16(uint32_t saddr, const void* g) {
    asm volatile("cp.async.cg.shared.global [%0], [%1], 16;" :: "r"(saddr), "l"(g));
}
#define CP_COMMIT() asm volatile("cp.async.commit_group;" ::: "memory")
#define CP_WAIT(n)  asm volatile("cp.async.wait_group %0;" :: "n"(n) : "memory")

__device__ __forceinline__ float shfl_sum3(float v) {
    v += __shfl_xor_sync(0xffffffffu, v, 4);
    v += __shfl_xor_sync(0xffffffffu, v, 8);
    v += __shfl_xor_sync(0xffffffffu, v, 16);
    return v;
}
__device__ __forceinline__ float shfl_max3(float v) {
    v = fmaxf(v, __shfl_xor_sync(0xffffffffu, v, 4));
    v = fmaxf(v, __shfl_xor_sync(0xffffffffu, v, 8));
    v = fmaxf(v, __shfl_xor_sync(0xffffffffu, v, 16));
    return v;
}

// ---------------- stage 1: KNN, warp-per-trajectory, 8 warps/block -----------
__global__ __launch_bounds__(256) void knn_kernel(const float* __restrict__ pts)
{
    __shared__ float spts[NP*3];      // 12 KB shared by 8 warps (same b)
    __shared__ float d2w[8][NP];      // 32 KB
    __shared__ int   selw[8][KNN];

    int tid = threadIdx.x;
    int w = tid >> 5, lane = tid & 31;
    int gid = blockIdx.x*8 + w;       // trajectory id
    int b = gid >> 10, i = gid & 1023;

    float cx = pts[((size_t)(b*T_)*NP + i)*3 + 0];
    float cy = pts[((size_t)(b*T_)*NP + i)*3 + 1];
    float cz = pts[((size_t)(b*T_)*NP + i)*3 + 2];
    float ax = 0.f, ay = 0.f, az = 0.f;

    for (int t = 0; t < T_; t++) {
        const float* pt = pts + (size_t)(b*T_ + t)*NP*3;
        const float* pv = pts + (size_t)(b*T_ + (t == 0 ? 0 : t-1))*NP*3;
        for (int e = tid; e < NP*3; e += 256) spts[e] = pt[e];
        __syncthreads();
        for (int j = lane; j < NP; j += 32) {
            float dx = cx - spts[j*3+0];
            float dy = cy - spts[j*3+1];
            float dz = cz - spts[j*3+2];
            d2w[w][j] = dx*dx + dy*dy + dz*dz;
        }
        __syncwarp();
        for (int k = 0; k < KNN; k++) {
            float bv = FLT_MAX; int bj = NP;
            #pragma unroll
            for (int m = 0; m < NP/32; m++) {
                int j = lane + m*32;
                float v = d2w[w][j];
                if (v < bv) { bv = v; bj = j; }
            }
            #pragma unroll
            for (int off = 16; off; off >>= 1) {
                float ov = __shfl_xor_sync(0xffffffffu, bv, off);
                int   oj = __shfl_xor_sync(0xffffffffu, bj, off);
                if (ov < bv || (ov == bv && oj < bj)) { bv = ov; bj = oj; }
            }
            if (lane == 0) { selw[w][k] = bj; d2w[w][bj] = FLT_MAX; }
            __syncwarp();
            if (k == 0 && t == 0) {
                ax = spts[bj*3+0]; ay = spts[bj*3+1]; az = spts[bj*3+2];
            }
        }
        size_t basef = ((size_t)((b*T_ + t)*NP) + i) * KNN;
        if (lane < KNN) {
            int sj = selw[w][lane];
            float* dst = g_feats + (basef + lane)*6;
            dst[0] = pv[sj*3+0]; dst[1] = pv[sj*3+1]; dst[2] = pv[sj*3+2];
            dst[3] = spts[sj*3+0] - ax; dst[4] = spts[sj*3+1] - ay; dst[5] = spts[sj*3+2] - az;
        }
        int s0 = selw[w][0];
        cx = spts[s0*3+0]; cy = spts[s0*3+1]; cz = spts[s0*3+2];
        __syncthreads();
    }
}

// ---------------- layer 0 (6 -> 64) with per-block BN partials ----------------
__global__ __launch_bounds__(256) void mlp0_kernel(const float* __restrict__ w,
                                                   const float* __restrict__ bias)
{
    __shared__ float sf[64][C0];
    __shared__ float sw[C1*C0];
    __shared__ float sb[C1];
    __shared__ float2 red[4][C1];
    int tid = threadIdx.y*64 + threadIdx.x;
    int p0 = blockIdx.x * 64;
    for (int e = tid; e < 64*C0; e += 256) sf[e/C0][e%C0] = g_feats[(size_t)p0*C0 + e];
    for (int e = tid; e < C1*C0; e += 256) sw[e] = w[e];
    if (tid < C1) sb[tid] = bias[tid];
    __syncthreads();
    int c = threadIdx.x;
    float lw[C0];
    #pragma unroll
    for (int j = 0; j < C0; j++) lw[j] = sw[c*C0+j];
    float bsv = sb[c];
    float lsum = 0.f, lsq = 0.f;
    for (int pi = threadIdx.y; pi < 64; pi += 4) {
        float acc = bsv;
        #pragma unroll
        for (int j = 0; j < C0; j++) acc += sf[pi][j]*lw[j];
        g_h0[(size_t)(p0+pi)*C1 + c] = acc;
        lsum += acc; lsq += acc*acc;
    }
    red[threadIdx.y][c] = make_float2(lsum, lsq);
    __syncthreads();
    if (threadIdx.y == 0) {
        float s = 0.f, q = 0.f;
        #pragma unroll
        for (int r = 0; r < 4; r++) { s += red[r][c].x; q += red[r][c].y; }
        g_pA[blockIdx.x*C1 + c] = s;
        g_pB[blockIdx.x*C1 + c] = q;
    }
}

// ---------------- fold BN stats ----------------
__global__ void fold_kernel(int nblk, int C, float cnt,
                            const float* __restrict__ g, const float* __restrict__ be,
                            int slot)
{
    int c = threadIdx.x;
    if (c >= C) return;
    double s = 0.0, q = 0.0;
    for (int r = 0; r < nblk; r++) { s += (double)g_pA[r*C + c]; q += (double)g_pB[r*C + c]; }
    double m = s / (double)cnt;
    double v = q / (double)cnt - m*m;
    float sc = g[c] * rsqrtf((float)v + EPSV);
    g_scale[slot*256 + c] = sc;
    g_shift[slot*256 + c] = be[c] - (float)m * sc;
}

// ---------------- weight prep ----------------
__global__ void prepw_kernel(const float* __restrict__ W, int N, int Cin,
                             __nv_bfloat16* __restrict__ dst)
{
    int i = blockIdx.x*256 + threadIdx.x;
    if (i >= N*Cin) return;
    int n = i / Cin, c = i % Cin;
    int chunk = c >> 6, k = c & 63;
    float w = W[i];
    __nv_bfloat16 h = __float2bfloat16_rn(w);
    float lo = w - __bfloat162float(h);
    int off = SWZ(n*128 + k*2) >> 1;
    size_t base = (size_t)chunk * (2*N*64);
    dst[base + off] = h;
    dst[base + N*64 + off] = __float2bfloat16_rn(lo);
}

__global__ void prepwt_kernel(const float* __restrict__ wt)
{
    int i = blockIdx.x*256 + threadIdx.x;
    if (i >= C3*C3*3) return;
    int dt = i % 3;
    int c  = (i / 3) % C3;
    int o  = i / (3*C3);
    int chunk = dt*4 + (c >> 6);
    int k = c & 63;
    float w = wt[i];
    __nv_bfloat16 h = __float2bfloat16_rn(w);
    float lo = w - __bfloat162float(h);
    int off = SWZ(o*128 + k*2) >> 1;
    size_t base = (size_t)chunk * (2*C3*64);
    g_wtx[base + off] = h;
    g_wtx[base + C3*64 + off] = __float2bfloat16_rn(lo);
}

// ---------------- activation convert: fp32 raw -> affine+relu -> split bf16 ---
// Output tiles: per (rowBlock, chunk): [hi 16KB][lo 16KB], swizzled like weights.
template<int CIN>
__global__ __launch_bounds__(256) void cvt_kernel(const float* __restrict__ src,
                                                  __nv_bfloat16* __restrict__ dst,
                                                  int affSlot)
{
    __shared__ float sS[64], sC[64];
    int tid = threadIdx.x;
    if (tid < 64) {
        sS[tid] = g_scale[affSlot*256 + blockIdx.y*64 + tid];
        sC[tid] = g_shift[affSlot*256 + blockIdx.y*64 + tid];
    }
    __syncthreads();
    char* out = (char*)dst + ((size_t)blockIdx.x*gridDim.y + blockIdx.y)*32768;
    const float* Ab = src + (size_t)blockIdx.x*128*CIN + blockIdx.y*64;
    #pragma unroll
    for (int i = 0; i < 8; i++) {
        int f = tid + i*256;
        int row = f >> 4;
        int k = (f & 15) * 4;
        float4 v = *(const float4*)(Ab + (size_t)row*CIN + k);
        v.x = fmaxf(fmaf(v.x, sS[k+0], sC[k+0]), 0.f);
        v.y = fmaxf(fmaf(v.y, sS[k+1], sC[k+1]), 0.f);
        v.z = fmaxf(fmaf(v.z, sS[k+2], sC[k+2]), 0.f);
        v.w = fmaxf(fmaf(v.w, sS[k+3], sC[k+3]), 0.f);
        float h0 = __bfloat162float(__float2bfloat16_rn(v.x));
        float h1 = __bfloat162float(__float2bfloat16_rn(v.y));
        float h2 = __bfloat162float(__float2bfloat16_rn(v.z));
        float h3 = __bfloat162float(__float2bfloat16_rn(v.w));
        uint32_t off = SWZ((uint32_t)(row*128 + k*2));
        *(uint2*)(out + off)         = make_uint2(pkbf(v.x, v.y), pkbf(v.z, v.w));
        *(uint2*)(out + 16384 + off) = make_uint2(pkbf(v.x - h0, v.y - h1), pkbf(v.z - h2, v.w - h3));
    }
}

// ---------------- pure-MMA GEMM: A pre-converted tiles, W pre-split ----------
// SMEM: A0[0,32K) A1[32K,64K) W0[64K,96K) W1[96K,128K) bias ps pq
#define OFF_A0   0
#define OFF_A1   32768
#define OFF_W0   65536
#define OFF_W1   98304
#define OFF_BIAS 131072
#define OFF_PS   131584
#define OFF_PQ   132608
#define SMB_GEMM 133632

template<int CIN, int COUT, int NCHUNK, int MODE>
__global__ __launch_bounds__(256, 1) void mma_gemm(
    const __nv_bfloat16* __restrict__ Ax, const __nv_bfloat16* __restrict__ Wx,
    const float* __restrict__ bias,
    float* __restrict__ out, float* __restrict__ pA, float* __restrict__ pB)
{
    extern __shared__ __align__(1024) char smem[];
    const int tid = threadIdx.x;
    const int wid = tid >> 5, lane = tid & 31;
    const int warpRow = wid & 1, warpCol = wid >> 1;
    const int rowBase = blockIdx.x * 128;
    const int colBase = blockIdx.y * 128;
    const uint32_t sb32 = smem_u32(smem);

    float* sbias = (float*)(smem + OFF_BIAS);
    if (tid < 128) sbias[tid] = bias[colBase + tid];

    int bb = 0, to = 0, n0 = 0;
    if (MODE == 2) { bb = rowBase/(TOUT*NP); to = (rowBase/NP) % TOUT; n0 = rowBase % NP; }

    auto a_tile = [&](int chunk) -> size_t {
        if (MODE == 2) {
            int dt = chunk >> 2, kc = chunk & 3;
            int rb = (bb*T_ + to + dt)*(NP/128) + (n0 >> 7);
            return ((size_t)rb*4 + kc)*32768;
        }
        return ((size_t)blockIdx.x*NCHUNK + chunk)*32768;
    };
    auto issue = [&](int chunk) {
        uint32_t abase = (chunk & 1) ? OFF_A1 : OFF_A0;
        uint32_t wbase = (chunk & 1) ? OFF_W1 : OFF_W0;
        const char* As = (const char*)Ax + a_tile(chunk);
        #pragma unroll
        for (int i = 0; i < 8; i++) {
            int o = (tid + i*256) * 16;
            cpasync16(sb32 + abase + o, As + o);
        }
        const char* Whi = (const char*)(Wx + (size_t)chunk*2*((size_t)COUT*64) + (size_t)colBase*64);
        const char* Wlo = (const char*)(Wx + (size_t)chunk*2*((size_t)COUT*64) + (size_t)COUT*64 + (size_t)colBase*64);
        #pragma unroll
        for (int i = 0; i < 4; i++) {
            int o = (tid + i*256) * 16;
            cpasync16(sb32 + wbase + o,         Whi + o);
            cpasync16(sb32 + wbase + 16384 + o, Wlo + o);
        }
        CP_COMMIT();
    };

    float acc[4][4][4] = {};

    issue(0);
    if (NCHUNK > 1) issue(1);

    for (int chunk = 0; chunk < NCHUNK; chunk++) {
        if (chunk + 1 < NCHUNK) { CP_WAIT(1); } else { CP_WAIT(0); }
        __syncthreads();
        uint32_t abase = (chunk & 1) ? OFF_A1 : OFF_A0;
        uint32_t wbase = (chunk & 1) ? OFF_W1 : OFF_W0;
        #pragma unroll
        for (int ks = 0; ks < 4; ks++) {
            uint32_t bh[4][2], bl[4][2];
            #pragma unroll
            for (int nt2 = 0; nt2 < 2; nt2++) {
                uint32_t roff = (uint32_t)((warpCol*32 + nt2*16 + ((lane>>4)<<3) + (lane&7))*128
                                           + ks*32 + (((lane>>3)&1)<<4));
                uint32_t ah = sb32 + wbase + SWZ(roff);
                uint32_t al = sb32 + wbase + 16384 + SWZ(roff);
                ldm_x4(ah, bh[nt2*2][0], bh[nt2*2][1], bh[nt2*2+1][0], bh[nt2*2+1][1]);
                ldm_x4(al, bl[nt2*2][0], bl[nt2*2][1], bl[nt2*2+1][0], bl[nt2*2+1][1]);
            }
            #pragma unroll
            for (int mt = 0; mt < 4; mt++) {
                uint32_t roff = (uint32_t)((warpRow*64 + mt*16 + (lane&15))*128
                                           + ks*32 + ((lane>>4)<<4));
                uint32_t ahreg[4], alreg[4];
                ldm_x4(sb32 + abase + SWZ(roff), ahreg[0], ahreg[1], ahreg[2], ahreg[3]);
                ldm_x4(sb32 + abase + 16384 + SWZ(roff), alreg[0], alreg[1], alreg[2], alreg[3]);
                #pragma unroll
                for (int nt = 0; nt < 4; nt++) mma16816(acc[mt][nt], ahreg, bh[nt]);
                #pragma unroll
                for (int nt = 0; nt < 4; nt++) mma16816(acc[mt][nt], ahreg, bl[nt]);
                #pragma unroll
                for (int nt = 0; nt < 4; nt++) mma16816(acc[mt][nt], alreg, bh[nt]);
            }
        }
        __syncthreads();
        if (chunk + 2 < NCHUNK) issue(chunk + 2);
    }

    // -------- epilogue --------
    #pragma unroll
    for (int nt = 0; nt < 4; nt++) {
        int cl = warpCol*32 + nt*8 + (lane&3)*2;
        float b0 = sbias[cl], b1 = sbias[cl+1];
        #pragma unroll
        for (int mt = 0; mt < 4; mt++) {
            acc[mt][nt][0] += b0; acc[mt][nt][1] += b1;
            acc[mt][nt][2] += b0; acc[mt][nt][3] += b1;
        }
    }
    float* ps = (float*)(smem + OFF_PS);
    float* pq = (float*)(smem + OFF_PQ);
    #pragma unroll
    for (int nt = 0; nt < 4; nt++) {
        float s0 = 0.f, s1 = 0.f, q0 = 0.f, q1 = 0.f;
        #pragma unroll
        for (int mt = 0; mt < 4; mt++) {
            float c0 = acc[mt][nt][0], c1 = acc[mt][nt][1];
            float c2 = acc[mt][nt][2], c3 = acc[mt][nt][3];
            s0 += c0 + c2; s1 += c1 + c3;
            q0 += c0*c0 + c2*c2; q1 += c1*c1 + c3*c3;
        }
        s0 = shfl_sum3(s0); s1 = shfl_sum3(s1);
        q0 = shfl_sum3(q0); q1 = shfl_sum3(q1);
        if (lane < 4) {
            int cl = warpCol*32 + nt*8 + lane*2;
            ps[warpRow*128 + cl] = s0; ps[warpRow*128 + cl + 1] = s1;
            pq[warpRow*128 + cl] = q0; pq[warpRow*128 + cl + 1] = q1;
        }
    }
    if (MODE == 1) {
        #pragma unroll
        for (int mt = 0; mt < 4; mt++) {
            int grow = (rowBase >> 4) + warpRow*4 + mt;
            #pragma unroll
            for (int nt = 0; nt < 4; nt++) {
                float m0 = shfl_max3(fmaxf(acc[mt][nt][0], acc[mt][nt][2]));
                float m1 = shfl_max3(fmaxf(acc[mt][nt][1], acc[mt][nt][3]));
                if (lane < 4) {
                    int cl = colBase + warpCol*32 + nt*8 + lane*2;
                    *(float2*)&out[(size_t)grow*COUT + cl] = make_float2(m0, m1);
                }
            }
        }
    } else {
        float* tile = (float*)smem;   // reuses A0/A1/W0 (dead; cp.async drained)
        __syncthreads();
        #pragma unroll
        for (int mt = 0; mt < 4; mt++) {
            int r0 = warpRow*64 + mt*16 + (lane >> 2);
            #pragma unroll
            for (int nt = 0; nt < 4; nt++) {
                int cl = warpCol*32 + nt*8 + (lane&3)*2;
                *(float2*)&tile[(r0)*132 + cl]   = make_float2(acc[mt][nt][0], acc[mt][nt][1]);
                *(float2*)&tile[(r0+8)*132 + cl] = make_float2(acc[mt][nt][2], acc[mt][nt][3]);
            }
        }
        __syncthreads();
        int r = tid >> 1, half = (tid & 1)*64;
        const float* src = tile + r*132 + half;
        float* dst = out + (size_t)(rowBase + r)*COUT + colBase + half;
        #pragma unroll
        for (int i = 0; i < 16; i++)
            *(float4*)(dst + i*4) = *(const float4*)(src + i*4);
    }
    __syncthreads();
    if (tid < 128) {
        pA[(size_t)blockIdx.x*COUT + colBase + tid] = ps[tid] + ps[128 + tid];
        pB[(size_t)blockIdx.x*COUT + colBase + tid] = pq[tid] + pq[128 + tid];
    }
}

// ---------------- final BN + relu -> output ----------------
__global__ void final_kernel(float* __restrict__ out)
{
    int i = blockIdx.x*blockDim.x + threadIdx.x;
    if (i < PT*C3) {
        int c = i & 255;
        out[i] = fmaxf(g_y[i]*g_scale[3*256 + c] + g_shift[3*256 + c], 0.f);
    }
}

// ---------------- launch ----------------
extern "C" void kernel_launch(void* const* d_in, const int* in_sizes, int n_in,
                              void* d_out, int out_size)
{
    (void)in_sizes; (void)n_in; (void)out_size;
    const float* pts = (const float*)d_in[0];
    const float* w0  = (const float*)d_in[1];
    const float* b0  = (const float*)d_in[2];
    const float* gg0 = (const float*)d_in[3];
    const float* be0 = (const float*)d_in[4];
    const float* w1  = (const float*)d_in[5];
    const float* b1  = (const float*)d_in[6];
    const float* gg1 = (const float*)d_in[7];
    const float* be1 = (const float*)d_in[8];
    const float* w2  = (const float*)d_in[9];
    const float* b2  = (const float*)d_in[10];
    const float* gg2 = (const float*)d_in[11];
    const float* be2 = (const float*)d_in[12];
    const float* wt  = (const float*)d_in[13];
    const float* bt  = (const float*)d_in[14];
    const float* ggt = (const float*)d_in[15];
    const float* bet = (const float*)d_in[16];
    float* out = (float*)d_out;

    float *dh0 = nullptr, *dh1 = nullptr, *dxm = nullptr, *dy = nullptr;
    float *dpA = nullptr, *dpB = nullptr;
    __nv_bfloat16 *dw1x = nullptr, *dw2x = nullptr, *dwtx = nullptr;
    __nv_bfloat16 *dh0x = nullptr, *dh1x = nullptr, *dxmx = nullptr;
    cudaGetSymbolAddress((void**)&dh0, g_h0);
    cudaGetSymbolAddress((void**)&dh1, g_h1);
    cudaGetSymbolAddress((void**)&dxm, g_xm);
    cudaGetSymbolAddress((void**)&dy, g_y);
    cudaGetSymbolAddress((void**)&dpA, g_pA);
    cudaGetSymbolAddress((void**)&dpB, g_pB);
    cudaGetSymbolAddress((void**)&dw1x, g_w1x);
    cudaGetSymbolAddress((void**)&dw2x, g_w2x);
    cudaGetSymbolAddress((void**)&dwtx, g_wtx);
    cudaGetSymbolAddress((void**)&dh0x, g_h0x);
    cudaGetSymbolAddress((void**)&dh1x, g_h1x);
    cudaGetSymbolAddress((void**)&dxmx, g_xmx);

    static bool attr_set = false;
    if (!attr_set) {
        cudaFuncSetAttribute(mma_gemm<64,128,1,0>,   cudaFuncAttributeMaxDynamicSharedMemorySize, SMB_GEMM);
        cudaFuncSetAttribute(mma_gemm<128,256,2,1>,  cudaFuncAttributeMaxDynamicSharedMemorySize, SMB_GEMM);
        cudaFuncSetAttribute(mma_gemm<256,256,12,2>, cudaFuncAttributeMaxDynamicSharedMemorySize, SMB_GEMM);
        attr_set = true;
    }

    prepw_kernel<<<(C2*C1 + 255)/256, 256>>>(w1, C2, C1, dw1x);
    prepw_kernel<<<(C3*C2 + 255)/256, 256>>>(w2, C3, C2, dw2x);
    prepwt_kernel<<<(C3*C3*3 + 255)/256, 256>>>(wt);
    knn_kernel<<<B_*NP/8, 256>>>(pts);

    mlp0_kernel<<<P1/64, dim3(64,4)>>>(w0, b0);
    fold_kernel<<<1, C1>>>(P1/64, C1, (float)P1, gg0, be0, 0);
    cvt_kernel<C1><<<dim3(P1/128, 1), 256>>>(dh0, dh0x, 0);

    mma_gemm<64,128,1,0><<<dim3(P1/128, 1), 256, SMB_GEMM>>>(dh0x, dw1x, b1, dh1, dpA, dpB);
    fold_kernel<<<1, C2>>>(P1/128, C2, (float)P1, gg1, be1, 1);
    cvt_kernel<C2><<<dim3(P1/128, 2), 256>>>(dh1, dh1x, 1);

    mma_gemm<128,256,2,1><<<dim3(P1/128, 2), 256, SMB_GEMM>>>(dh1x, dw2x, b2, dxm, dpA, dpB);
    fold_kernel<<<1, C3>>>(P1/128, C3, (float)P1, gg2, be2, 2);
    cvt_kernel<C3><<<dim3(PM/128, 4), 256>>>(dxm, dxmx, 2);

    mma_gemm<256,256,12,2><<<dim3(PT/128, 2), 256, SMB_GEMM>>>(dxmx, dwtx, bt, dy, dpA, dpB);
    fold_kernel<<<1, C3>>>(PT/128, C3, (float)PT, ggt, bet, 3);

    final_kernel<<<(PT*C3 + 255)/256, 256>>>(out);
}

// round 7
// speedup vs baseline: 3.3474x; 3.3474x over previous
#include <cuda_runtime.h>
#include <cuda_fp16.h>
#include <cfloat>
#include <cstdint>
#include <cstddef>

#define B_  2
#define T_  16
#define NP  1024
#define KNN 16
#define TOUT 14
#define C0 6
#define C1 64
#define C2 128
#define C3 256
#define EPSV 1e-5f

#define P1 (B_*T_*NP*KNN)
#define PM (B_*T_*NP)
#define PT (B_*TOUT*NP)

// ---------------- scratch ----------------
__device__ float g_feats[(size_t)P1*C0];
__device__ float g_h0[(size_t)P1*C1];
__device__ float g_h1[(size_t)P1*C2];
__device__ float g_xm[(size_t)PM*C3];
__device__ float g_y[(size_t)PT*C3];
__device__ float g_pA[(P1/128)*C3];
__device__ float g_pB[(P1/128)*C3];
__device__ float g_scale[4*256];
__device__ float g_shift[4*256];
// fp16 weights, single plane, swizzled per chunk [N x 64]
__device__ __half g_w2x[2*256*64];
__device__ __half g_wtx[12*256*64];
// pre-converted split-fp16 activations: per (rowblock,chunk) tile [hi 16KB][lo 16KB]
__device__ __half g_h1x[(size_t)P1*C2*2];
__device__ __half g_xmx[(size_t)PM*C3*2];

#define SWZ(x) ((x) ^ (((x) >> 3) & 0x70))

__device__ __forceinline__ uint32_t smem_u32(const void* p) {
    uint32_t a;
    asm("{ .reg .u64 t; cvta.to.shared.u64 t, %1; cvt.u32.u64 %0, t; }" : "=r"(a) : "l"(p));
    return a;
}
__device__ __forceinline__ uint32_t pkh(float a, float b) {
    __half2 h = __floats2half2_rn(a, b);
    return *reinterpret_cast<uint32_t*>(&h);
}
__device__ __forceinline__ void ldm_x4(uint32_t addr, uint32_t& r0, uint32_t& r1,
                                       uint32_t& r2, uint32_t& r3) {
    asm volatile("ldmatrix.sync.aligned.m8n8.x4.shared.b16 {%0,%1,%2,%3}, [%4];"
                 : "=r"(r0), "=r"(r1), "=r"(r2), "=r"(r3) : "r"(addr));
}
__device__ __forceinline__ void mma16816h(float* d, const uint32_t* a, const uint32_t* b) {
    asm volatile("mma.sync.aligned.m16n8k16.row.col.f32.f16.f16.f32 "
        "{%0,%1,%2,%3}, {%4,%5,%6,%7}, {%8,%9}, {%0,%1,%2,%3};"
        : "+f"(d[0]), "+f"(d[1]), "+f"(d[2]), "+f"(d[3])
        : "r"(a[0]), "r"(a[1]), "r"(a[2]), "r"(a[3]), "r"(b[0]), "r"(b[1]));
}
__device__ __forceinline__ void cpasync16(uint32_t saddr, const void* g) {
    asm volatile("cp.async.cg.shared.global [%0], [%1], 16;" :: "r"(saddr), "l"(g));
}
#define CP_COMMIT() asm volatile("cp.async.commit_group;" ::: "memory")
#define CP_WAIT(n)  asm volatile("cp.async.wait_group %0;" :: "n"(n) : "memory")

__device__ __forceinline__ float shfl_sum3(float v) {
    v += __shfl_xor_sync(0xffffffffu, v, 4);
    v += __shfl_xor_sync(0xffffffffu, v, 8);
    v += __shfl_xor_sync(0xffffffffu, v, 16);
    return v;
}
__device__ __forceinline__ float shfl_max3(float v) {
    v = fmaxf(v, __shfl_xor_sync(0xffffffffu, v, 4));
    v = fmaxf(v, __shfl_xor_sync(0xffffffffu, v, 8));
    v = fmaxf(v, __shfl_xor_sync(0xffffffffu, v, 16));
    return v;
}

// ---------------- stage 1: KNN, warp-per-trajectory ----------------
__global__ __launch_bounds__(256) void knn_kernel(const float* __restrict__ pts)
{
    __shared__ float spts[NP*3];
    __shared__ float d2w[8][NP];
    __shared__ int   selw[8][KNN];

    int tid = threadIdx.x;
    int w = tid >> 5, lane = tid & 31;
    int gid = blockIdx.x*8 + w;
    int b = gid >> 10, i = gid & 1023;

    float cx = pts[((size_t)(b*T_)*NP + i)*3 + 0];
    float cy = pts[((size_t)(b*T_)*NP + i)*3 + 1];
    float cz = pts[((size_t)(b*T_)*NP + i)*3 + 2];
    float ax = 0.f, ay = 0.f, az = 0.f;

    for (int t = 0; t < T_; t++) {
        const float* pt = pts + (size_t)(b*T_ + t)*NP*3;
        const float* pv = pts + (size_t)(b*T_ + (t == 0 ? 0 : t-1))*NP*3;
        for (int e = tid; e < NP*3; e += 256) spts[e] = pt[e];
        __syncthreads();
        for (int j = lane; j < NP; j += 32) {
            float dx = cx - spts[j*3+0];
            float dy = cy - spts[j*3+1];
            float dz = cz - spts[j*3+2];
            d2w[w][j] = dx*dx + dy*dy + dz*dz;
        }
        __syncwarp();
        for (int k = 0; k < KNN; k++) {
            float bv = FLT_MAX; int bj = NP;
            #pragma unroll
            for (int m = 0; m < NP/32; m++) {
                int j = lane + m*32;
                float v = d2w[w][j];
                if (v < bv) { bv = v; bj = j; }
            }
            #pragma unroll
            for (int off = 16; off; off >>= 1) {
                float ov = __shfl_xor_sync(0xffffffffu, bv, off);
                int   oj = __shfl_xor_sync(0xffffffffu, bj, off);
                if (ov < bv || (ov == bv && oj < bj)) { bv = ov; bj = oj; }
            }
            if (lane == 0) { selw[w][k] = bj; d2w[w][bj] = FLT_MAX; }
            __syncwarp();
            if (k == 0 && t == 0) {
                ax = spts[bj*3+0]; ay = spts[bj*3+1]; az = spts[bj*3+2];
            }
        }
        size_t basef = ((size_t)((b*T_ + t)*NP) + i) * KNN;
        if (lane < KNN) {
            int sj = selw[w][lane];
            float* dst = g_feats + (basef + lane)*6;
            dst[0] = pv[sj*3+0]; dst[1] = pv[sj*3+1]; dst[2] = pv[sj*3+2];
            dst[3] = spts[sj*3+0] - ax; dst[4] = spts[sj*3+1] - ay; dst[5] = spts[sj*3+2] - az;
        }
        int s0 = selw[w][0];
        cx = spts[s0*3+0]; cy = spts[s0*3+1]; cz = spts[s0*3+2];
        __syncthreads();
    }
}

// ---------------- layer 0 (6 -> 64) with per-block BN partials ----------------
__global__ __launch_bounds__(256) void mlp0_kernel(const float* __restrict__ w,
                                                   const float* __restrict__ bias)
{
    __shared__ float sf[64][C0];
    __shared__ float sw[C1*C0];
    __shared__ float sb[C1];
    __shared__ float2 red[4][C1];
    int tid = threadIdx.y*64 + threadIdx.x;
    int p0 = blockIdx.x * 64;
    for (int e = tid; e < 64*C0; e += 256) sf[e/C0][e%C0] = g_feats[(size_t)p0*C0 + e];
    for (int e = tid; e < C1*C0; e += 256) sw[e] = w[e];
    if (tid < C1) sb[tid] = bias[tid];
    __syncthreads();
    int c = threadIdx.x;
    float lw[C0];
    #pragma unroll
    for (int j = 0; j < C0; j++) lw[j] = sw[c*C0+j];
    float bsv = sb[c];
    float lsum = 0.f, lsq = 0.f;
    for (int pi = threadIdx.y; pi < 64; pi += 4) {
        float acc = bsv;
        #pragma unroll
        for (int j = 0; j < C0; j++) acc += sf[pi][j]*lw[j];
        g_h0[(size_t)(p0+pi)*C1 + c] = acc;
        lsum += acc; lsq += acc*acc;
    }
    red[threadIdx.y][c] = make_float2(lsum, lsq);
    __syncthreads();
    if (threadIdx.y == 0) {
        float s = 0.f, q = 0.f;
        #pragma unroll
        for (int r = 0; r < 4; r++) { s += red[r][c].x; q += red[r][c].y; }
        g_pA[blockIdx.x*C1 + c] = s;
        g_pB[blockIdx.x*C1 + c] = q;
    }
}

// ---------------- fold BN stats (one block per channel) ----------------
__global__ void fold_kernel(int nblk, int C, float cnt,
                            const float* __restrict__ g, const float* __restrict__ be,
                            int slot)
{
    int c = blockIdx.x;
    double s = 0.0, q = 0.0;
    for (int r = threadIdx.x; r < nblk; r += 256) {
        s += (double)g_pA[r*C + c];
        q += (double)g_pB[r*C + c];
    }
    __shared__ double sh[512];
    sh[threadIdx.x] = s; sh[256 + threadIdx.x] = q;
    __syncthreads();
    for (int o = 128; o; o >>= 1) {
        if (threadIdx.x < o) {
            sh[threadIdx.x] += sh[threadIdx.x + o];
            sh[256 + threadIdx.x] += sh[256 + threadIdx.x + o];
        }
        __syncthreads();
    }
    if (threadIdx.x == 0) {
        double m = sh[0] / (double)cnt;
        double v = sh[256] / (double)cnt - m*m;
        float sc = g[c] * rsqrtf((float)v + EPSV);
        g_scale[slot*256 + c] = sc;
        g_shift[slot*256 + c] = be[c] - (float)m * sc;
    }
}

// ---------------- weight prep: fp32 -> fp16, pre-swizzled chunk images -------
__global__ void prepw_kernel(const float* __restrict__ W, int N, int Cin,
                             __half* __restrict__ dst)
{
    int i = blockIdx.x*256 + threadIdx.x;
    if (i >= N*Cin) return;
    int n = i / Cin, c = i % Cin;
    int chunk = c >> 6, k = c & 63;
    int off = SWZ(n*128 + k*2) >> 1;
    dst[(size_t)chunk*(N*64) + off] = __float2half_rn(W[i]);
}

__global__ void prepwt_kernel(const float* __restrict__ wt)
{
    int i = blockIdx.x*256 + threadIdx.x;
    if (i >= C3*C3*3) return;
    int dt = i % 3;
    int c  = (i / 3) % C3;
    int o  = i / (3*C3);
    int chunk = dt*4 + (c >> 6);
    int k = c & 63;
    int off = SWZ(o*128 + k*2) >> 1;
    g_wtx[(size_t)chunk*(C3*64) + off] = __float2half_rn(wt[i]);
}

// ---------------- activation convert: affine+relu -> split fp16 tiles --------
template<int CIN>
__global__ __launch_bounds__(256) void cvt_kernel(const float* __restrict__ src,
                                                  __half* __restrict__ dst,
                                                  int affSlot)
{
    __shared__ float sS[64], sC[64];
    int tid = threadIdx.x;
    if (tid < 64) {
        sS[tid] = g_scale[affSlot*256 + blockIdx.y*64 + tid];
        sC[tid] = g_shift[affSlot*256 + blockIdx.y*64 + tid];
    }
    __syncthreads();
    char* out = (char*)dst + ((size_t)blockIdx.x*gridDim.y + blockIdx.y)*32768;
    const float* Ab = src + (size_t)blockIdx.x*128*CIN + blockIdx.y*64;
    #pragma unroll
    for (int i = 0; i < 8; i++) {
        int f = tid + i*256;
        int row = f >> 4;
        int k = (f & 15) * 4;
        float4 v = *(const float4*)(Ab + (size_t)row*CIN + k);
        v.x = fmaxf(fmaf(v.x, sS[k+0], sC[k+0]), 0.f);
        v.y = fmaxf(fmaf(v.y, sS[k+1], sC[k+1]), 0.f);
        v.z = fmaxf(fmaf(v.z, sS[k+2], sC[k+2]), 0.f);
        v.w = fmaxf(fmaf(v.w, sS[k+3], sC[k+3]), 0.f);
        float h0 = __half2float(__float2half_rn(v.x));
        float h1 = __half2float(__float2half_rn(v.y));
        float h2 = __half2float(__float2half_rn(v.z));
        float h3 = __half2float(__float2half_rn(v.w));
        uint32_t off = SWZ((uint32_t)(row*128 + k*2));
        *(uint2*)(out + off)         = make_uint2(pkh(v.x, v.y), pkh(v.z, v.w));
        *(uint2*)(out + 16384 + off) = make_uint2(pkh(v.x - h0, v.y - h1), pkh(v.z - h2, v.w - h3));
    }
}

// ---------------- gemm1: 64->128, inline A+W convert (launch #4: profiled) ---
#define OFF1_AHI  0
#define OFF1_ALO  16384
#define OFF1_W    32768
#define OFF1_SS   49152
#define OFF1_SC   49408
#define OFF1_BIAS 67584
#define OFF1_PS   68096
#define OFF1_PQ   69120
#define SMB1      70144

__global__ __launch_bounds__(256, 2) void mma_gemm1(
    const float* __restrict__ A, const float* __restrict__ W,
    const float* __restrict__ bias,
    float* __restrict__ out, float* __restrict__ pA, float* __restrict__ pB)
{
    extern __shared__ __align__(1024) char smem[];
    const int tid = threadIdx.x;
    const int wid = tid >> 5, lane = tid & 31;
    const int warpRow = wid & 1, warpCol = wid >> 1;
    const int rowBase = blockIdx.x * 128;
    const uint32_t sb32 = smem_u32(smem);

    float* sS = (float*)(smem + OFF1_SS);
    float* sC = (float*)(smem + OFF1_SC);
    float* sbias = (float*)(smem + OFF1_BIAS);
    if (tid < 64) { sS[tid] = g_scale[tid]; sC[tid] = g_shift[tid]; }
    if (tid < 128) sbias[tid] = bias[tid];
    __syncthreads();

    // W convert: w1 [128][64] fp32 -> fp16 swizzled
    for (int i = tid; i < 128*64; i += 256) {
        int n = i >> 6, c = i & 63;
        *(__half*)(smem + OFF1_W + SWZ(n*128 + c*2)) = __float2half_rn(W[i]);
    }
    // A convert: h0 -> affine+relu -> split fp16
    {
        const float* Ab = A + (size_t)rowBase*64;
        #pragma unroll
        for (int i = 0; i < 8; i++) {
            int f = tid + i*256;
            int row = f >> 4;
            int k = (f & 15) * 4;
            float4 v = *(const float4*)(Ab + (size_t)row*64 + k);
            v.x = fmaxf(fmaf(v.x, sS[k+0], sC[k+0]), 0.f);
            v.y = fmaxf(fmaf(v.y, sS[k+1], sC[k+1]), 0.f);
            v.z = fmaxf(fmaf(v.z, sS[k+2], sC[k+2]), 0.f);
            v.w = fmaxf(fmaf(v.w, sS[k+3], sC[k+3]), 0.f);
            float h0 = __half2float(__float2half_rn(v.x));
            float h1 = __half2float(__float2half_rn(v.y));
            float h2 = __half2float(__float2half_rn(v.z));
            float h3 = __half2float(__float2half_rn(v.w));
            uint32_t off = SWZ((uint32_t)(row*128 + k*2));
            *(uint2*)(smem + OFF1_AHI + off) = make_uint2(pkh(v.x, v.y), pkh(v.z, v.w));
            *(uint2*)(smem + OFF1_ALO + off) = make_uint2(pkh(v.x - h0, v.y - h1), pkh(v.z - h2, v.w - h3));
        }
    }
    __syncthreads();

    float acc[4][4][4] = {};
    #pragma unroll
    for (int ks = 0; ks < 4; ks++) {
        uint32_t bh[4][2];
        #pragma unroll
        for (int nt2 = 0; nt2 < 2; nt2++) {
            uint32_t roff = (uint32_t)((warpCol*32 + nt2*16 + ((lane>>4)<<3) + (lane&7))*128
                                       + ks*32 + (((lane>>3)&1)<<4));
            ldm_x4(sb32 + OFF1_W + SWZ(roff), bh[nt2*2][0], bh[nt2*2][1], bh[nt2*2+1][0], bh[nt2*2+1][1]);
        }
        #pragma unroll
        for (int mt = 0; mt < 4; mt++) {
            uint32_t roff = (uint32_t)((warpRow*64 + mt*16 + (lane&15))*128
                                       + ks*32 + ((lane>>4)<<4));
            uint32_t ah[4], al[4];
            ldm_x4(sb32 + OFF1_AHI + SWZ(roff), ah[0], ah[1], ah[2], ah[3]);
            ldm_x4(sb32 + OFF1_ALO + SWZ(roff), al[0], al[1], al[2], al[3]);
            #pragma unroll
            for (int nt = 0; nt < 4; nt++) mma16816h(acc[mt][nt], ah, bh[nt]);
            #pragma unroll
            for (int nt = 0; nt < 4; nt++) mma16816h(acc[mt][nt], al, bh[nt]);
        }
    }

    // epilogue: bias + BN partials + coalesced raw store (COUT=128)
    #pragma unroll
    for (int nt = 0; nt < 4; nt++) {
        int cl = warpCol*32 + nt*8 + (lane&3)*2;
        float b0 = sbias[cl], b1 = sbias[cl+1];
        #pragma unroll
        for (int mt = 0; mt < 4; mt++) {
            acc[mt][nt][0] += b0; acc[mt][nt][1] += b1;
            acc[mt][nt][2] += b0; acc[mt][nt][3] += b1;
        }
    }
    float* ps = (float*)(smem + OFF1_PS);
    float* pq = (float*)(smem + OFF1_PQ);
    #pragma unroll
    for (int nt = 0; nt < 4; nt++) {
        float s0 = 0.f, s1 = 0.f, q0 = 0.f, q1 = 0.f;
        #pragma unroll
        for (int mt = 0; mt < 4; mt++) {
            float c0 = acc[mt][nt][0], c1 = acc[mt][nt][1];
            float c2 = acc[mt][nt][2], c3 = acc[mt][nt][3];
            s0 += c0 + c2; s1 += c1 + c3;
            q0 += c0*c0 + c2*c2; q1 += c1*c1 + c3*c3;
        }
        s0 = shfl_sum3(s0); s1 = shfl_sum3(s1);
        q0 = shfl_sum3(q0); q1 = shfl_sum3(q1);
        if (lane < 4) {
            int cl = warpCol*32 + nt*8 + lane*2;
            ps[warpRow*128 + cl] = s0; ps[warpRow*128 + cl + 1] = s1;
            pq[warpRow*128 + cl] = q0; pq[warpRow*128 + cl + 1] = q1;
        }
    }
    float* tile = (float*)smem;
    __syncthreads();
    #pragma unroll
    for (int mt = 0; mt < 4; mt++) {
        int r0 = warpRow*64 + mt*16 + (lane >> 2);
        #pragma unroll
        for (int nt = 0; nt < 4; nt++) {
            int cl = warpCol*32 + nt*8 + (lane&3)*2;
            *(float2*)&tile[(r0)*132 + cl]   = make_float2(acc[mt][nt][0], acc[mt][nt][1]);
            *(float2*)&tile[(r0+8)*132 + cl] = make_float2(acc[mt][nt][2], acc[mt][nt][3]);
        }
    }
    __syncthreads();
    {
        int r = tid >> 1, half = (tid & 1)*64;
        const float* src = tile + r*132 + half;
        float* dst = out + (size_t)(rowBase + r)*C2 + half;
        #pragma unroll
        for (int i = 0; i < 16; i++)
            *(float4*)(dst + i*4) = *(const float4*)(src + i*4);
    }
    __syncthreads();
    if (tid < 128) {
        pA[(size_t)blockIdx.x*C2 + tid] = ps[tid] + ps[128 + tid];
        pB[(size_t)blockIdx.x*C2 + tid] = pq[tid] + pq[128 + tid];
    }
}

// ---------------- general GEMM: A pre-converted tiles, W fp16 plane ----------
// SMEM: A0[0,32K) A1[32K,64K) W0[64K,80K) W1[80K,96K) bias ps pq
#define OFF_A0   0
#define OFF_A1   32768
#define OFF_W0   65536
#define OFF_W1   81920
#define OFF_BIAS 98304
#define OFF_PS   98816
#define OFF_PQ   99840
#define SMB_GEMM 100864

template<int COUT, int NCHUNK, int MODE>
__global__ __launch_bounds__(256, 2) void mma_gemm(
    const __half* __restrict__ Ax, const __half* __restrict__ Wx,
    const float* __restrict__ bias,
    float* __restrict__ out, float* __restrict__ pA, float* __restrict__ pB)
{
    extern __shared__ __align__(1024) char smem[];
    const int tid = threadIdx.x;
    const int wid = tid >> 5, lane = tid & 31;
    const int warpRow = wid & 1, warpCol = wid >> 1;
    const int rowBase = blockIdx.x * 128;
    const int colBase = blockIdx.y * 128;
    const uint32_t sb32 = smem_u32(smem);

    float* sbias = (float*)(smem + OFF_BIAS);
    if (tid < 128) sbias[tid] = bias[colBase + tid];

    int bb = 0, to = 0, n0 = 0;
    if (MODE == 2) { bb = rowBase/(TOUT*NP); to = (rowBase/NP) % TOUT; n0 = rowBase % NP; }

    auto a_tile = [&](int chunk) -> size_t {
        if (MODE == 2) {
            int dt = chunk >> 2, kc = chunk & 3;
            int rb = (bb*T_ + to + dt)*(NP/128) + (n0 >> 7);
            return ((size_t)rb*4 + kc)*32768;
        }
        return ((size_t)blockIdx.x*NCHUNK + chunk)*32768;
    };
    auto issue = [&](int chunk) {
        uint32_t abase = (chunk & 1) ? OFF_A1 : OFF_A0;
        uint32_t wbase = (chunk & 1) ? OFF_W1 : OFF_W0;
        const char* As = (const char*)Ax + a_tile(chunk);
        #pragma unroll
        for (int i = 0; i < 8; i++) {
            int o = (tid + i*256) * 16;
            cpasync16(sb32 + abase + o, As + o);
        }
        const char* Wp = (const char*)(Wx + (size_t)chunk*((size_t)COUT*64) + (size_t)colBase*64);
        #pragma unroll
        for (int i = 0; i < 4; i++) {
            int o = (tid + i*256) * 16;
            cpasync16(sb32 + wbase + o, Wp + o);
        }
        CP_COMMIT();
    };

    float acc[4][4][4] = {};

    issue(0);
    if (NCHUNK > 1) issue(1);

    for (int chunk = 0; chunk < NCHUNK; chunk++) {
        if (chunk + 1 < NCHUNK) { CP_WAIT(1); } else { CP_WAIT(0); }
        __syncthreads();
        uint32_t abase = (chunk & 1) ? OFF_A1 : OFF_A0;
        uint32_t wbase = (chunk & 1) ? OFF_W1 : OFF_W0;
        #pragma unroll
        for (int ks = 0; ks < 4; ks++) {
            uint32_t bh[4][2];
            #pragma unroll
            for (int nt2 = 0; nt2 < 2; nt2++) {
                uint32_t roff = (uint32_t)((warpCol*32 + nt2*16 + ((lane>>4)<<3) + (lane&7))*128
                                           + ks*32 + (((lane>>3)&1)<<4));
                ldm_x4(sb32 + wbase + SWZ(roff), bh[nt2*2][0], bh[nt2*2][1], bh[nt2*2+1][0], bh[nt2*2+1][1]);
            }
            #pragma unroll
            for (int mt = 0; mt < 4; mt++) {
                uint32_t roff = (uint32_t)((warpRow*64 + mt*16 + (lane&15))*128
                                           + ks*32 + ((lane>>4)<<4));
                uint32_t ah[4], al[4];
                ldm_x4(sb32 + abase + SWZ(roff), ah[0], ah[1], ah[2], ah[3]);
                ldm_x4(sb32 + abase + 16384 + SWZ(roff), al[0], al[1], al[2], al[3]);
                #pragma unroll
                for (int nt = 0; nt < 4; nt++) mma16816h(acc[mt][nt], ah, bh[nt]);
                #pragma unroll
                for (int nt = 0; nt < 4; nt++) mma16816h(acc[mt][nt], al, bh[nt]);
            }
        }
        __syncthreads();
        if (chunk + 2 < NCHUNK) issue(chunk + 2);
    }

    // -------- epilogue --------
    #pragma unroll
    for (int nt = 0; nt < 4; nt++) {
        int cl = warpCol*32 + nt*8 + (lane&3)*2;
        float b0 = sbias[cl], b1 = sbias[cl+1];
        #pragma unroll
        for (int mt = 0; mt < 4; mt++) {
            acc[mt][nt][0] += b0; acc[mt][nt][1] += b1;
            acc[mt][nt][2] += b0; acc[mt][nt][3] += b1;
        }
    }
    float* ps = (float*)(smem + OFF_PS);
    float* pq = (float*)(smem + OFF_PQ);
    #pragma unroll
    for (int nt = 0; nt < 4; nt++) {
        float s0 = 0.f, s1 = 0.f, q0 = 0.f, q1 = 0.f;
        #pragma unroll
        for (int mt = 0; mt < 4; mt++) {
            float c0 = acc[mt][nt][0], c1 = acc[mt][nt][1];
            float c2 = acc[mt][nt][2], c3 = acc[mt][nt][3];
            s0 += c0 + c2; s1 += c1 + c3;
            q0 += c0*c0 + c2*c2; q1 += c1*c1 + c3*c3;
        }
        s0 = shfl_sum3(s0); s1 = shfl_sum3(s1);
        q0 = shfl_sum3(q0); q1 = shfl_sum3(q1);
        if (lane < 4) {
            int cl = warpCol*32 + nt*8 + lane*2;
            ps[warpRow*128 + cl] = s0; ps[warpRow*128 + cl + 1] = s1;
            pq[warpRow*128 + cl] = q0; pq[warpRow*128 + cl + 1] = q1;
        }
    }
    if (MODE == 1) {
        #pragma unroll
        for (int mt = 0; mt < 4; mt++) {
            int grow = (rowBase >> 4) + warpRow*4 + mt;
            #pragma unroll
            for (int nt = 0; nt < 4; nt++) {
                float m0 = shfl_max3(fmaxf(acc[mt][nt][0], acc[mt][nt][2]));
                float m1 = shfl_max3(fmaxf(acc[mt][nt][1], acc[mt][nt][3]));
                if (lane < 4) {
                    int cl = colBase + warpCol*32 + nt*8 + lane*2;
                    *(float2*)&out[(size_t)grow*COUT + cl] = make_float2(m0, m1);
                }
            }
        }
    } else {
        float* tile = (float*)smem;
        __syncthreads();
        #pragma unroll
        for (int mt = 0; mt < 4; mt++) {
            int r0 = warpRow*64 + mt*16 + (lane >> 2);
            #pragma unroll
            for (int nt = 0; nt < 4; nt++) {
                int cl = warpCol*32 + nt*8 + (lane&3)*2;
                *(float2*)&tile[(r0)*132 + cl]   = make_float2(acc[mt][nt][0], acc[mt][nt][1]);
                *(float2*)&tile[(r0+8)*132 + cl] = make_float2(acc[mt][nt][2], acc[mt][nt][3]);
            }
        }
        __syncthreads();
        int r = tid >> 1, half = (tid & 1)*64;
        const float* src = tile + r*132 + half;
        float* dst = out + (size_t)(rowBase + r)*COUT + colBase + half;
        #pragma unroll
        for (int i = 0; i < 16; i++)
            *(float4*)(dst + i*4) = *(const float4*)(src + i*4);
    }
    __syncthreads();
    if (tid < 128) {
        pA[(size_t)blockIdx.x*COUT + colBase + tid] = ps[tid] + ps[128 + tid];
        pB[(size_t)blockIdx.x*COUT + colBase + tid] = pq[tid] + pq[128 + tid];
    }
}

// ---------------- final BN + relu -> output ----------------
__global__ void final_kernel(float* __restrict__ out)
{
    int i = blockIdx.x*blockDim.x + threadIdx.x;
    if (i < PT*C3) {
        int c = i & 255;
        out[i] = fmaxf(g_y[i]*g_scale[3*256 + c] + g_shift[3*256 + c], 0.f);
    }
}

// ---------------- launch ----------------
extern "C" void kernel_launch(void* const* d_in, const int* in_sizes, int n_in,
                              void* d_out, int out_size)
{
    (void)in_sizes; (void)n_in; (void)out_size;
    const float* pts = (const float*)d_in[0];
    const float* w0  = (const float*)d_in[1];
    const float* b0  = (const float*)d_in[2];
    const float* gg0 = (const float*)d_in[3];
    const float* be0 = (const float*)d_in[4];
    const float* w1  = (const float*)d_in[5];
    const float* b1  = (const float*)d_in[6];
    const float* gg1 = (const float*)d_in[7];
    const float* be1 = (const float*)d_in[8];
    const float* w2  = (const float*)d_in[9];
    const float* b2  = (const float*)d_in[10];
    const float* gg2 = (const float*)d_in[11];
    const float* be2 = (const float*)d_in[12];
    const float* wt  = (const float*)d_in[13];
    const float* bt  = (const float*)d_in[14];
    const float* ggt = (const float*)d_in[15];
    const float* bet = (const float*)d_in[16];
    float* out = (float*)d_out;

    float *dh0 = nullptr, *dh1 = nullptr, *dxm = nullptr, *dy = nullptr;
    float *dpA = nullptr, *dpB = nullptr;
    __half *dw2x = nullptr, *dwtx = nullptr, *dh1x = nullptr, *dxmx = nullptr;
    cudaGetSymbolAddress((void**)&dh0, g_h0);
    cudaGetSymbolAddress((void**)&dh1, g_h1);
    cudaGetSymbolAddress((void**)&dxm, g_xm);
    cudaGetSymbolAddress((void**)&dy, g_y);
    cudaGetSymbolAddress((void**)&dpA, g_pA);
    cudaGetSymbolAddress((void**)&dpB, g_pB);
    cudaGetSymbolAddress((void**)&dw2x, g_w2x);
    cudaGetSymbolAddress((void**)&dwtx, g_wtx);
    cudaGetSymbolAddress((void**)&dh1x, g_h1x);
    cudaGetSymbolAddress((void**)&dxmx, g_xmx);

    static bool attr_set = false;
    if (!attr_set) {
        cudaFuncSetAttribute(mma_gemm1,         cudaFuncAttributeMaxDynamicSharedMemorySize, SMB1);
        cudaFuncSetAttribute(mma_gemm<256,2,1>, cudaFuncAttributeMaxDynamicSharedMemorySize, SMB_GEMM);
        cudaFuncSetAttribute(mma_gemm<256,12,2>,cudaFuncAttributeMaxDynamicSharedMemorySize, SMB_GEMM);
        attr_set = true;
    }

    // launch order chosen so mma_gemm1 is launch #4 (profiler window)
    knn_kernel<<<B_*NP/8, 256>>>(pts);
    mlp0_kernel<<<P1/64, dim3(64,4)>>>(w0, b0);
    fold_kernel<<<C1, 256>>>(P1/64, C1, (float)P1, gg0, be0, 0);

    mma_gemm1<<<P1/128, 256, SMB1>>>(dh0, w1, b1, dh1, dpA, dpB);
    fold_kernel<<<C2, 256>>>(P1/128, C2, (float)P1, gg1, be1, 1);

    prepw_kernel<<<(C3*C2 + 255)/256, 256>>>(w2, C3, C2, dw2x);
    cvt_kernel<C2><<<dim3(P1/128, 2), 256>>>(dh1, dh1x, 1);
    mma_gemm<256,2,1><<<dim3(P1/128, 2), 256, SMB_GEMM>>>(dh1x, dw2x, b2, dxm, dpA, dpB);
    fold_kernel<<<C3, 256>>>(P1/128, C3, (float)P1, gg2, be2, 2);

    prepwt_kernel<<<(C3*C3*3 + 255)/256, 256>>>(wt);
    cvt_kernel<C3><<<dim3(PM/128, 4), 256>>>(dxm, dxmx, 2);
    mma_gemm<256,12,2><<<dim3(PT/128, 2), 256, SMB_GEMM>>>(dxmx, dwtx, bt, dy, dpA, dpB);
    fold_kernel<<<C3, 256>>>(PT/128, C3, (float)PT, ggt, bet, 3);

    final_kernel<<<(PT*C3 + 255)/256, 256>>>(out);
}

// round 8
// speedup vs baseline: 3.7943x; 1.1335x over previous
#include <cuda_runtime.h>
#include <cuda_fp16.h>
#include <cfloat>
#include <cstdint>
#include <cstddef>

#define B_  2
#define T_  16
#define NP  1024
#define KNN 16
#define TOUT 14
#define C0 6
#define C1 64
#define C2 128
#define C3 256
#define EPSV 1e-5f

#define P1 (B_*T_*NP*KNN)
#define PM (B_*T_*NP)
#define PT (B_*TOUT*NP)

// ---------------- scratch ----------------
__device__ float g_feats[(size_t)P1*C0];
__device__ float g_curs[(size_t)B_*T_*NP*3];
__device__ float g_h0[(size_t)P1*C1];
__device__ float g_h1[(size_t)P1*C2];
__device__ float g_xm[(size_t)PM*C3];
__device__ float g_y[(size_t)PT*C3];
__device__ float g_pA[(P1/128)*C3];
__device__ float g_pB[(P1/128)*C3];
__device__ float g_scale[4*256];
__device__ float g_shift[4*256];
__device__ __half g_w2x[2*256*64];
__device__ __half g_wtx[12*256*64];
__device__ __half g_h1x[(size_t)P1*C2*2];
__device__ __half g_xmx[(size_t)PM*C3*2];

#define SWZ(x) ((x) ^ (((x) >> 3) & 0x70))

__device__ __forceinline__ uint32_t smem_u32(const void* p) {
    uint32_t a;
    asm("{ .reg .u64 t; cvta.to.shared.u64 t, %1; cvt.u32.u64 %0, t; }" : "=r"(a) : "l"(p));
    return a;
}
__device__ __forceinline__ uint32_t pkh(float a, float b) {
    __half2 h = __floats2half2_rn(a, b);
    return *reinterpret_cast<uint32_t*>(&h);
}
__device__ __forceinline__ void ldm_x4(uint32_t addr, uint32_t& r0, uint32_t& r1,
                                       uint32_t& r2, uint32_t& r3) {
    asm volatile("ldmatrix.sync.aligned.m8n8.x4.shared.b16 {%0,%1,%2,%3}, [%4];"
                 : "=r"(r0), "=r"(r1), "=r"(r2), "=r"(r3) : "r"(addr));
}
__device__ __forceinline__ void mma16816h(float* d, const uint32_t* a, const uint32_t* b) {
    asm volatile("mma.sync.aligned.m16n8k16.row.col.f32.f16.f16.f32 "
        "{%0,%1,%2,%3}, {%4,%5,%6,%7}, {%8,%9}, {%0,%1,%2,%3};"
        : "+f"(d[0]), "+f"(d[1]), "+f"(d[2]), "+f"(d[3])
        : "r"(a[0]), "r"(a[1]), "r"(a[2]), "r"(a[3]), "r"(b[0]), "r"(b[1]));
}
__device__ __forceinline__ void cpasync16(uint32_t saddr, const void* g) {
    asm volatile("cp.async.cg.shared.global [%0], [%1], 16;" :: "r"(saddr), "l"(g));
}
#define CP_COMMIT() asm volatile("cp.async.commit_group;" ::: "memory")
#define CP_WAIT(n)  asm volatile("cp.async.wait_group %0;" :: "n"(n) : "memory")

__device__ __forceinline__ float shfl_sum3(float v) {
    v += __shfl_xor_sync(0xffffffffu, v, 4);
    v += __shfl_xor_sync(0xffffffffu, v, 8);
    v += __shfl_xor_sync(0xffffffffu, v, 16);
    return v;
}
__device__ __forceinline__ float shfl_max3(float v) {
    v = fmaxf(v, __shfl_xor_sync(0xffffffffu, v, 4));
    v = fmaxf(v, __shfl_xor_sync(0xffffffffu, v, 8));
    v = fmaxf(v, __shfl_xor_sync(0xffffffffu, v, 16));
    return v;
}

// ---------------- stage 1a: trajectory pass (argmin chain only) --------------
__global__ __launch_bounds__(256) void traj_kernel(const float* __restrict__ pts)
{
    __shared__ float spts[NP*3];
    int tid = threadIdx.x;
    int w = tid >> 5, lane = tid & 31;
    int gid = blockIdx.x*8 + w;
    int b = gid >> 10, i = gid & 1023;

    float cx = pts[((size_t)(b*T_)*NP + i)*3 + 0];
    float cy = pts[((size_t)(b*T_)*NP + i)*3 + 1];
    float cz = pts[((size_t)(b*T_)*NP + i)*3 + 2];

    for (int t = 0; t < T_; t++) {
        const float* pt = pts + (size_t)(b*T_ + t)*NP*3;
        for (int e = tid; e < NP*3; e += 256) spts[e] = pt[e];
        __syncthreads();
        if (lane == 0) {
            float* c = g_curs + ((size_t)(b*T_ + t)*NP + i)*3;
            c[0] = cx; c[1] = cy; c[2] = cz;
        }
        float bv = FLT_MAX; int bj = NP;
        #pragma unroll
        for (int m = 0; m < NP/32; m++) {
            int j = lane + m*32;
            float dx = cx - spts[j*3+0];
            float dy = cy - spts[j*3+1];
            float dz = cz - spts[j*3+2];
            float v = dx*dx + dy*dy + dz*dz;
            if (v < bv) { bv = v; bj = j; }
        }
        #pragma unroll
        for (int off = 16; off; off >>= 1) {
            float ov = __shfl_xor_sync(0xffffffffu, bv, off);
            int   oj = __shfl_xor_sync(0xffffffffu, bj, off);
            if (ov < bv || (ov == bv && oj < bj)) { bv = ov; bj = oj; }
        }
        cx = spts[bj*3+0]; cy = spts[bj*3+1]; cz = spts[bj*3+2];
        __syncthreads();
    }
}

// ---------------- stage 1b: parallel top-16 + feature write ------------------
// grid: (b,t) x 128 groups; 8 warps/block, warp = one n. Dynamic smem.
__global__ __launch_bounds__(256) void topk_kernel(const float* __restrict__ pts)
{
    extern __shared__ float sm[];
    float* spts = sm;              // 3072
    float* pv   = sm + 3072;       // 3072
    float* d2w  = sm + 6144;       // 8*1024
    int*   selw = (int*)(sm + 6144 + 8192);  // 8*16

    int tid = threadIdx.x;
    int w = tid >> 5, lane = tid & 31;
    int bt  = blockIdx.x >> 7;
    int grp = blockIdx.x & 127;
    int b = bt >> 4, t = bt & 15;
    int n = grp*8 + w;

    const float* pt = pts + (size_t)(b*T_ + t)*NP*3;
    const float* pp = pts + (size_t)(b*T_ + (t == 0 ? 0 : t-1))*NP*3;
    for (int e = tid; e < NP*3; e += 256) { spts[e] = pt[e]; pv[e] = pp[e]; }
    __syncthreads();

    const float* cq = g_curs + ((size_t)bt*NP + n)*3;
    float cx = cq[0], cy = cq[1], cz = cq[2];
    const float* aq = g_curs + ((size_t)(b*T_ + 1)*NP + n)*3;
    float ax = aq[0], ay = aq[1], az = aq[2];

    for (int j = lane; j < NP; j += 32) {
        float dx = cx - spts[j*3+0];
        float dy = cy - spts[j*3+1];
        float dz = cz - spts[j*3+2];
        d2w[w*NP + j] = dx*dx + dy*dy + dz*dz;
    }
    __syncwarp();
    for (int k = 0; k < KNN; k++) {
        float bv = FLT_MAX; int bj = NP;
        #pragma unroll
        for (int m = 0; m < NP/32; m++) {
            int j = lane + m*32;
            float v = d2w[w*NP + j];
            if (v < bv) { bv = v; bj = j; }
        }
        #pragma unroll
        for (int off = 16; off; off >>= 1) {
            float ov = __shfl_xor_sync(0xffffffffu, bv, off);
            int   oj = __shfl_xor_sync(0xffffffffu, bj, off);
            if (ov < bv || (ov == bv && oj < bj)) { bv = ov; bj = oj; }
        }
        if (lane == 0) { selw[w*KNN + k] = bj; d2w[w*NP + bj] = FLT_MAX; }
        __syncwarp();
    }
    size_t basef = ((size_t)bt*NP + n) * KNN;
    if (lane < KNN) {
        int sj = selw[w*KNN + lane];
        float* dst = g_feats + (basef + lane)*6;
        dst[0] = pv[sj*3+0]; dst[1] = pv[sj*3+1]; dst[2] = pv[sj*3+2];
        dst[3] = spts[sj*3+0] - ax; dst[4] = spts[sj*3+1] - ay; dst[5] = spts[sj*3+2] - az;
    }
}

// ---------------- layer 0 (6 -> 64) with per-block BN partials ----------------
__global__ __launch_bounds__(256) void mlp0_kernel(const float* __restrict__ w,
                                                   const float* __restrict__ bias)
{
    __shared__ float sf[64][C0];
    __shared__ float sw[C1*C0];
    __shared__ float sb[C1];
    __shared__ float2 red[4][C1];
    int tid = threadIdx.y*64 + threadIdx.x;
    int p0 = blockIdx.x * 64;
    for (int e = tid; e < 64*C0; e += 256) sf[e/C0][e%C0] = g_feats[(size_t)p0*C0 + e];
    for (int e = tid; e < C1*C0; e += 256) sw[e] = w[e];
    if (tid < C1) sb[tid] = bias[tid];
    __syncthreads();
    int c = threadIdx.x;
    float lw[C0];
    #pragma unroll
    for (int j = 0; j < C0; j++) lw[j] = sw[c*C0+j];
    float bsv = sb[c];
    float lsum = 0.f, lsq = 0.f;
    for (int pi = threadIdx.y; pi < 64; pi += 4) {
        float acc = bsv;
        #pragma unroll
        for (int j = 0; j < C0; j++) acc += sf[pi][j]*lw[j];
        g_h0[(size_t)(p0+pi)*C1 + c] = acc;
        lsum += acc; lsq += acc*acc;
    }
    red[threadIdx.y][c] = make_float2(lsum, lsq);
    __syncthreads();
    if (threadIdx.y == 0) {
        float s = 0.f, q = 0.f;
        #pragma unroll
        for (int r = 0; r < 4; r++) { s += red[r][c].x; q += red[r][c].y; }
        g_pA[blockIdx.x*C1 + c] = s;
        g_pB[blockIdx.x*C1 + c] = q;
    }
}

// ---------------- fold BN stats (one block per channel) ----------------
__global__ void fold_kernel(int nblk, int C, float cnt,
                            const float* __restrict__ g, const float* __restrict__ be,
                            int slot)
{
    int c = blockIdx.x;
    double s = 0.0, q = 0.0;
    for (int r = threadIdx.x; r < nblk; r += 256) {
        s += (double)g_pA[r*C + c];
        q += (double)g_pB[r*C + c];
    }
    __shared__ double sh[512];
    sh[threadIdx.x] = s; sh[256 + threadIdx.x] = q;
    __syncthreads();
    for (int o = 128; o; o >>= 1) {
        if (threadIdx.x < o) {
            sh[threadIdx.x] += sh[threadIdx.x + o];
            sh[256 + threadIdx.x] += sh[256 + threadIdx.x + o];
        }
        __syncthreads();
    }
    if (threadIdx.x == 0) {
        double m = sh[0] / (double)cnt;
        double v = sh[256] / (double)cnt - m*m;
        float sc = g[c] * rsqrtf((float)v + EPSV);
        g_scale[slot*256 + c] = sc;
        g_shift[slot*256 + c] = be[c] - (float)m * sc;
    }
}

// ---------------- weight prep ----------------
__global__ void prepw_kernel(const float* __restrict__ W, int N, int Cin,
                             __half* __restrict__ dst)
{
    int i = blockIdx.x*256 + threadIdx.x;
    if (i >= N*Cin) return;
    int n = i / Cin, c = i % Cin;
    int chunk = c >> 6, k = c & 63;
    int off = SWZ(n*128 + k*2) >> 1;
    dst[(size_t)chunk*(N*64) + off] = __float2half_rn(W[i]);
}

__global__ void prepwt_kernel(const float* __restrict__ wt)
{
    int i = blockIdx.x*256 + threadIdx.x;
    if (i >= C3*C3*3) return;
    int dt = i % 3;
    int c  = (i / 3) % C3;
    int o  = i / (3*C3);
    int chunk = dt*4 + (c >> 6);
    int k = c & 63;
    int off = SWZ(o*128 + k*2) >> 1;
    g_wtx[(size_t)chunk*(C3*64) + off] = __float2half_rn(wt[i]);
}

// ---------------- activation convert: affine+relu -> split fp16 tiles --------
template<int CIN>
__global__ __launch_bounds__(256) void cvt_kernel(const float* __restrict__ src,
                                                  __half* __restrict__ dst,
                                                  int affSlot)
{
    __shared__ float sS[64], sC[64];
    int tid = threadIdx.x;
    if (tid < 64) {
        sS[tid] = g_scale[affSlot*256 + blockIdx.y*64 + tid];
        sC[tid] = g_shift[affSlot*256 + blockIdx.y*64 + tid];
    }
    __syncthreads();
    char* out = (char*)dst + ((size_t)blockIdx.x*gridDim.y + blockIdx.y)*32768;
    const float* Ab = src + (size_t)blockIdx.x*128*CIN + blockIdx.y*64;
    #pragma unroll
    for (int i = 0; i < 8; i++) {
        int f = tid + i*256;
        int row = f >> 4;
        int k = (f & 15) * 4;
        float4 v = *(const float4*)(Ab + (size_t)row*CIN + k);
        v.x = fmaxf(fmaf(v.x, sS[k+0], sC[k+0]), 0.f);
        v.y = fmaxf(fmaf(v.y, sS[k+1], sC[k+1]), 0.f);
        v.z = fmaxf(fmaf(v.z, sS[k+2], sC[k+2]), 0.f);
        v.w = fmaxf(fmaf(v.w, sS[k+3], sC[k+3]), 0.f);
        float h0 = __half2float(__float2half_rn(v.x));
        float h1 = __half2float(__float2half_rn(v.y));
        float h2 = __half2float(__float2half_rn(v.z));
        float h3 = __half2float(__float2half_rn(v.w));
        uint32_t off = SWZ((uint32_t)(row*128 + k*2));
        *(uint2*)(out + off)         = make_uint2(pkh(v.x, v.y), pkh(v.z, v.w));
        *(uint2*)(out + 16384 + off) = make_uint2(pkh(v.x - h0, v.y - h1), pkh(v.z - h2, v.w - h3));
    }
}

// ---------------- gemm1: 64->128, 4 row-tiles per block, pipelined -----------
#define OFFG_W    0
#define OFFG_RAW  16384
#define OFFG_AHI  49152
#define OFFG_ALO  65536
#define OFFG_SS   81920
#define OFFG_SC   82176
#define OFFG_BIAS 82432
#define OFFG_PS   82944
#define OFFG_PQ   83968
#define SMBG1     84992
#define G1_TILES  4

__global__ __launch_bounds__(256, 2) void mma_gemm1(
    const float* __restrict__ A, const float* __restrict__ W,
    const float* __restrict__ bias,
    float* __restrict__ out, float* __restrict__ pA, float* __restrict__ pB)
{
    extern __shared__ __align__(1024) char smem[];
    const int tid = threadIdx.x;
    const int wid = tid >> 5, lane = tid & 31;
    const int warpRow = wid & 1, warpCol = wid >> 1;
    const uint32_t sb32 = smem_u32(smem);

    float* sS = (float*)(smem + OFFG_SS);
    float* sC = (float*)(smem + OFFG_SC);
    float* sbias = (float*)(smem + OFFG_BIAS);
    if (tid < 64) { sS[tid] = g_scale[tid]; sC[tid] = g_shift[tid]; }
    if (tid < 128) sbias[tid] = bias[tid];
    // W convert once per block
    for (int i = tid; i < 128*64; i += 256) {
        int n = i >> 6, c = i & 63;
        *(__half*)(smem + OFFG_W + SWZ(n*128 + c*2)) = __float2half_rn(W[i]);
    }
    // prologue: cp.async raw A tile 0
    {
        const char* Ab = (const char*)(A + (size_t)(blockIdx.x*G1_TILES)*128*64);
        #pragma unroll
        for (int i = 0; i < 8; i++) {
            int o = (tid + i*256) * 16;
            cpasync16(sb32 + OFFG_RAW + o, Ab + o);
        }
        CP_COMMIT();
    }
    __syncthreads();   // sS/sC/W visible

    for (int tile = 0; tile < G1_TILES; tile++) {
        int rowBase = (blockIdx.x*G1_TILES + tile)*128;
        CP_WAIT(0);
        __syncthreads();  // raw tile visible to all
        // convert raw -> split fp16 (smem -> smem)
        #pragma unroll
        for (int i = 0; i < 8; i++) {
            int f = tid + i*256;
            int row = f >> 4;
            int k = (f & 15) * 4;
            float4 v = *(const float4*)(smem + OFFG_RAW + (row*64 + k)*4);
            v.x = fmaxf(fmaf(v.x, sS[k+0], sC[k+0]), 0.f);
            v.y = fmaxf(fmaf(v.y, sS[k+1], sC[k+1]), 0.f);
            v.z = fmaxf(fmaf(v.z, sS[k+2], sC[k+2]), 0.f);
            v.w = fmaxf(fmaf(v.w, sS[k+3], sC[k+3]), 0.f);
            float h0 = __half2float(__float2half_rn(v.x));
            float h1 = __half2float(__float2half_rn(v.y));
            float h2 = __half2float(__float2half_rn(v.z));
            float h3 = __half2float(__float2half_rn(v.w));
            uint32_t off = SWZ((uint32_t)(row*128 + k*2));
            *(uint2*)(smem + OFFG_AHI + off) = make_uint2(pkh(v.x, v.y), pkh(v.z, v.w));
            *(uint2*)(smem + OFFG_ALO + off) = make_uint2(pkh(v.x - h0, v.y - h1), pkh(v.z - h2, v.w - h3));
        }
        __syncthreads();  // ahi/alo ready; raw buffer free
        // prefetch next raw tile (overlaps MMA + epilogue)
        if (tile + 1 < G1_TILES) {
            const char* Ab = (const char*)(A + (size_t)(blockIdx.x*G1_TILES + tile + 1)*128*64);
            #pragma unroll
            for (int i = 0; i < 8; i++) {
                int o = (tid + i*256) * 16;
                cpasync16(sb32 + OFFG_RAW + o, Ab + o);
            }
            CP_COMMIT();
        }
        // MMA
        float acc[4][4][4] = {};
        #pragma unroll
        for (int ks = 0; ks < 4; ks++) {
            uint32_t bh[4][2];
            #pragma unroll
            for (int nt2 = 0; nt2 < 2; nt2++) {
                uint32_t roff = (uint32_t)((warpCol*32 + nt2*16 + ((lane>>4)<<3) + (lane&7))*128
                                           + ks*32 + (((lane>>3)&1)<<4));
                ldm_x4(sb32 + OFFG_W + SWZ(roff), bh[nt2*2][0], bh[nt2*2][1], bh[nt2*2+1][0], bh[nt2*2+1][1]);
            }
            #pragma unroll
            for (int mt = 0; mt < 4; mt++) {
                uint32_t roff = (uint32_t)((warpRow*64 + mt*16 + (lane&15))*128
                                           + ks*32 + ((lane>>4)<<4));
                uint32_t ah[4], al[4];
                ldm_x4(sb32 + OFFG_AHI + SWZ(roff), ah[0], ah[1], ah[2], ah[3]);
                ldm_x4(sb32 + OFFG_ALO + SWZ(roff), al[0], al[1], al[2], al[3]);
                #pragma unroll
                for (int nt = 0; nt < 4; nt++) mma16816h(acc[mt][nt], ah, bh[nt]);
                #pragma unroll
                for (int nt = 0; nt < 4; nt++) mma16816h(acc[mt][nt], al, bh[nt]);
            }
        }
        // epilogue: bias, BN partials, direct sector stores
        #pragma unroll
        for (int nt = 0; nt < 4; nt++) {
            int cl = warpCol*32 + nt*8 + (lane&3)*2;
            float b0 = sbias[cl], b1 = sbias[cl+1];
            #pragma unroll
            for (int mt = 0; mt < 4; mt++) {
                acc[mt][nt][0] += b0; acc[mt][nt][1] += b1;
                acc[mt][nt][2] += b0; acc[mt][nt][3] += b1;
            }
        }
        float* ps = (float*)(smem + OFFG_PS);
        float* pq = (float*)(smem + OFFG_PQ);
        #pragma unroll
        for (int nt = 0; nt < 4; nt++) {
            float s0 = 0.f, s1 = 0.f, q0 = 0.f, q1 = 0.f;
            #pragma unroll
            for (int mt = 0; mt < 4; mt++) {
                float c0 = acc[mt][nt][0], c1 = acc[mt][nt][1];
                float c2 = acc[mt][nt][2], c3 = acc[mt][nt][3];
                s0 += c0 + c2; s1 += c1 + c3;
                q0 += c0*c0 + c2*c2; q1 += c1*c1 + c3*c3;
            }
            s0 = shfl_sum3(s0); s1 = shfl_sum3(s1);
            q0 = shfl_sum3(q0); q1 = shfl_sum3(q1);
            if (lane < 4) {
                int cl = warpCol*32 + nt*8 + lane*2;
                ps[warpRow*128 + cl] = s0; ps[warpRow*128 + cl + 1] = s1;
                pq[warpRow*128 + cl] = q0; pq[warpRow*128 + cl + 1] = q1;
            }
        }
        #pragma unroll
        for (int mt = 0; mt < 4; mt++) {
            int r0 = rowBase + warpRow*64 + mt*16 + (lane >> 2);
            #pragma unroll
            for (int nt = 0; nt < 4; nt++) {
                int cl = warpCol*32 + nt*8 + (lane&3)*2;
                *(float2*)&out[(size_t)r0*C2 + cl]     = make_float2(acc[mt][nt][0], acc[mt][nt][1]);
                *(float2*)&out[(size_t)(r0+8)*C2 + cl] = make_float2(acc[mt][nt][2], acc[mt][nt][3]);
            }
        }
        __syncthreads();  // ps/pq complete
        if (tid < 128) {
            pA[(size_t)(blockIdx.x*G1_TILES + tile)*C2 + tid] = ps[tid] + ps[128 + tid];
            pB[(size_t)(blockIdx.x*G1_TILES + tile)*C2 + tid] = pq[tid] + pq[128 + tid];
        }
    }
}

// ---------------- general GEMM: A pre-converted tiles, W fp16 plane ----------
#define OFF_A0   0
#define OFF_A1   32768
#define OFF_W0   65536
#define OFF_W1   81920
#define OFF_BIAS 98304
#define OFF_PS   98816
#define OFF_PQ   99840
#define SMB_GEMM 100864

template<int COUT, int NCHUNK, int MODE>
__global__ __launch_bounds__(256, 2) void mma_gemm(
    const __half* __restrict__ Ax, const __half* __restrict__ Wx,
    const float* __restrict__ bias,
    float* __restrict__ out, float* __restrict__ pA, float* __restrict__ pB)
{
    extern __shared__ __align__(1024) char smem[];
    const int tid = threadIdx.x;
    const int wid = tid >> 5, lane = tid & 31;
    const int warpRow = wid & 1, warpCol = wid >> 1;
    const int rowBase = blockIdx.x * 128;
    const int colBase = blockIdx.y * 128;
    const uint32_t sb32 = smem_u32(smem);

    float* sbias = (float*)(smem + OFF_BIAS);
    if (tid < 128) sbias[tid] = bias[colBase + tid];

    int bb = 0, to = 0, n0 = 0;
    if (MODE == 2) { bb = rowBase/(TOUT*NP); to = (rowBase/NP) % TOUT; n0 = rowBase % NP; }

    auto a_tile = [&](int chunk) -> size_t {
        if (MODE == 2) {
            int dt = chunk >> 2, kc = chunk & 3;
            int rb = (bb*T_ + to + dt)*(NP/128) + (n0 >> 7);
            return ((size_t)rb*4 + kc)*32768;
        }
        return ((size_t)blockIdx.x*NCHUNK + chunk)*32768;
    };
    auto issue = [&](int chunk) {
        uint32_t abase = (chunk & 1) ? OFF_A1 : OFF_A0;
        uint32_t wbase = (chunk & 1) ? OFF_W1 : OFF_W0;
        const char* As = (const char*)Ax + a_tile(chunk);
        #pragma unroll
        for (int i = 0; i < 8; i++) {
            int o = (tid + i*256) * 16;
            cpasync16(sb32 + abase + o, As + o);
        }
        const char* Wp = (const char*)(Wx + (size_t)chunk*((size_t)COUT*64) + (size_t)colBase*64);
        #pragma unroll
        for (int i = 0; i < 4; i++) {
            int o = (tid + i*256) * 16;
            cpasync16(sb32 + wbase + o, Wp + o);
        }
        CP_COMMIT();
    };

    float acc[4][4][4] = {};

    issue(0);
    if (NCHUNK > 1) issue(1);

    for (int chunk = 0; chunk < NCHUNK; chunk++) {
        if (chunk + 1 < NCHUNK) { CP_WAIT(1); } else { CP_WAIT(0); }
        __syncthreads();
        uint32_t abase = (chunk & 1) ? OFF_A1 : OFF_A0;
        uint32_t wbase = (chunk & 1) ? OFF_W1 : OFF_W0;
        #pragma unroll
        for (int ks = 0; ks < 4; ks++) {
            uint32_t bh[4][2];
            #pragma unroll
            for (int nt2 = 0; nt2 < 2; nt2++) {
                uint32_t roff = (uint32_t)((warpCol*32 + nt2*16 + ((lane>>4)<<3) + (lane&7))*128
                                           + ks*32 + (((lane>>3)&1)<<4));
                ldm_x4(sb32 + wbase + SWZ(roff), bh[nt2*2][0], bh[nt2*2][1], bh[nt2*2+1][0], bh[nt2*2+1][1]);
            }
            #pragma unroll
            for (int mt = 0; mt < 4; mt++) {
                uint32_t roff = (uint32_t)((warpRow*64 + mt*16 + (lane&15))*128
                                           + ks*32 + ((lane>>4)<<4));
                uint32_t ah[4], al[4];
                ldm_x4(sb32 + abase + SWZ(roff), ah[0], ah[1], ah[2], ah[3]);
                ldm_x4(sb32 + abase + 16384 + SWZ(roff), al[0], al[1], al[2], al[3]);
                #pragma unroll
                for (int nt = 0; nt < 4; nt++) mma16816h(acc[mt][nt], ah, bh[nt]);
                #pragma unroll
                for (int nt = 0; nt < 4; nt++) mma16816h(acc[mt][nt], al, bh[nt]);
            }
        }
        __syncthreads();
        if (chunk + 2 < NCHUNK) issue(chunk + 2);
    }

    // -------- epilogue --------
    #pragma unroll
    for (int nt = 0; nt < 4; nt++) {
        int cl = warpCol*32 + nt*8 + (lane&3)*2;
        float b0 = sbias[cl], b1 = sbias[cl+1];
        #pragma unroll
        for (int mt = 0; mt < 4; mt++) {
            acc[mt][nt][0] += b0; acc[mt][nt][1] += b1;
            acc[mt][nt][2] += b0; acc[mt][nt][3] += b1;
        }
    }
    float* ps = (float*)(smem + OFF_PS);
    float* pq = (float*)(smem + OFF_PQ);
    #pragma unroll
    for (int nt = 0; nt < 4; nt++) {
        float s0 = 0.f, s1 = 0.f, q0 = 0.f, q1 = 0.f;
        #pragma unroll
        for (int mt = 0; mt < 4; mt++) {
            float c0 = acc[mt][nt][0], c1 = acc[mt][nt][1];
            float c2 = acc[mt][nt][2], c3 = acc[mt][nt][3];
            s0 += c0 + c2; s1 += c1 + c3;
            q0 += c0*c0 + c2*c2; q1 += c1*c1 + c3*c3;
        }
        s0 = shfl_sum3(s0); s1 = shfl_sum3(s1);
        q0 = shfl_sum3(q0); q1 = shfl_sum3(q1);
        if (lane < 4) {
            int cl = warpCol*32 + nt*8 + lane*2;
            ps[warpRow*128 + cl] = s0; ps[warpRow*128 + cl + 1] = s1;
            pq[warpRow*128 + cl] = q0; pq[warpRow*128 + cl + 1] = q1;
        }
    }
    if (MODE == 1) {
        #pragma unroll
        for (int mt = 0; mt < 4; mt++) {
            int grow = (rowBase >> 4) + warpRow*4 + mt;
            #pragma unroll
            for (int nt = 0; nt < 4; nt++) {
                float m0 = shfl_max3(fmaxf(acc[mt][nt][0], acc[mt][nt][2]));
                float m1 = shfl_max3(fmaxf(acc[mt][nt][1], acc[mt][nt][3]));
                if (lane < 4) {
                    int cl = colBase + warpCol*32 + nt*8 + lane*2;
                    *(float2*)&out[(size_t)grow*COUT + cl] = make_float2(m0, m1);
                }
            }
        }
    } else {
        float* tile = (float*)smem;
        __syncthreads();
        #pragma unroll
        for (int mt = 0; mt < 4; mt++) {
            int r0 = warpRow*64 + mt*16 + (lane >> 2);
            #pragma unroll
            for (int nt = 0; nt < 4; nt++) {
                int cl = warpCol*32 + nt*8 + (lane&3)*2;
                *(float2*)&tile[(r0)*132 + cl]   = make_float2(acc[mt][nt][0], acc[mt][nt][1]);
                *(float2*)&tile[(r0+8)*132 + cl] = make_float2(acc[mt][nt][2], acc[mt][nt][3]);
            }
        }
        __syncthreads();
        int r = tid >> 1, half = (tid & 1)*64;
        const float* src = tile + r*132 + half;
        float* dst = out + (size_t)(rowBase + r)*COUT + colBase + half;
        #pragma unroll
        for (int i = 0; i < 16; i++)
            *(float4*)(dst + i*4) = *(const float4*)(src + i*4);
    }
    __syncthreads();
    if (tid < 128) {
        pA[(size_t)blockIdx.x*COUT + colBase + tid] = ps[tid] + ps[128 + tid];
        pB[(size_t)blockIdx.x*COUT + colBase + tid] = pq[tid] + pq[128 + tid];
    }
}

// ---------------- final BN + relu -> output ----------------
__global__ void final_kernel(float* __restrict__ out)
{
    int i = blockIdx.x*blockDim.x + threadIdx.x;
    if (i < PT*C3) {
        int c = i & 255;
        out[i] = fmaxf(g_y[i]*g_scale[3*256 + c] + g_shift[3*256 + c], 0.f);
    }
}

// ---------------- launch ----------------
extern "C" void kernel_launch(void* const* d_in, const int* in_sizes, int n_in,
                              void* d_out, int out_size)
{
    (void)in_sizes; (void)n_in; (void)out_size;
    const float* pts = (const float*)d_in[0];
    const float* w0  = (const float*)d_in[1];
    const float* b0  = (const float*)d_in[2];
    const float* gg0 = (const float*)d_in[3];
    const float* be0 = (const float*)d_in[4];
    const float* w1  = (const float*)d_in[5];
    const float* b1  = (const float*)d_in[6];
    const float* gg1 = (const float*)d_in[7];
    const float* be1 = (const float*)d_in[8];
    const float* w2  = (const float*)d_in[9];
    const float* b2  = (const float*)d_in[10];
    const float* gg2 = (const float*)d_in[11];
    const float* be2 = (const float*)d_in[12];
    const float* wt  = (const float*)d_in[13];
    const float* bt  = (const float*)d_in[14];
    const float* ggt = (const float*)d_in[15];
    const float* bet = (const float*)d_in[16];
    float* out = (float*)d_out;

    float *dh0 = nullptr, *dh1 = nullptr, *dxm = nullptr, *dy = nullptr;
    float *dpA = nullptr, *dpB = nullptr;
    __half *dw2x = nullptr, *dwtx = nullptr, *dh1x = nullptr, *dxmx = nullptr;
    cudaGetSymbolAddress((void**)&dh0, g_h0);
    cudaGetSymbolAddress((void**)&dh1, g_h1);
    cudaGetSymbolAddress((void**)&dxm, g_xm);
    cudaGetSymbolAddress((void**)&dy, g_y);
    cudaGetSymbolAddress((void**)&dpA, g_pA);
    cudaGetSymbolAddress((void**)&dpB, g_pB);
    cudaGetSymbolAddress((void**)&dw2x, g_w2x);
    cudaGetSymbolAddress((void**)&dwtx, g_wtx);
    cudaGetSymbolAddress((void**)&dh1x, g_h1x);
    cudaGetSymbolAddress((void**)&dxmx, g_xmx);

    const int SMB_TOPK = (3072 + 3072 + 8*1024)*4 + 8*KNN*4;
    static bool attr_set = false;
    if (!attr_set) {
        cudaFuncSetAttribute(topk_kernel,       cudaFuncAttributeMaxDynamicSharedMemorySize, SMB_TOPK);
        cudaFuncSetAttribute(mma_gemm1,         cudaFuncAttributeMaxDynamicSharedMemorySize, SMBG1);
        cudaFuncSetAttribute(mma_gemm<256,2,1>, cudaFuncAttributeMaxDynamicSharedMemorySize, SMB_GEMM);
        cudaFuncSetAttribute(mma_gemm<256,12,2>,cudaFuncAttributeMaxDynamicSharedMemorySize, SMB_GEMM);
        attr_set = true;
    }

    prepw_kernel<<<(C3*C2 + 255)/256, 256>>>(w2, C3, C2, dw2x);
    prepwt_kernel<<<(C3*C3*3 + 255)/256, 256>>>(wt);
    traj_kernel<<<B_*NP/8, 256>>>(pts);
    topk_kernel<<<B_*T_*(NP/8)/1, 256, SMB_TOPK>>>(pts);   // 32*128 = 4096 blocks

    mlp0_kernel<<<P1/64, dim3(64,4)>>>(w0, b0);
    fold_kernel<<<C1, 256>>>(P1/64, C1, (float)P1, gg0, be0, 0);

    mma_gemm1<<<P1/128/G1_TILES, 256, SMBG1>>>(dh0, w1, b1, dh1, dpA, dpB);
    fold_kernel<<<C2, 256>>>(P1/128, C2, (float)P1, gg1, be1, 1);

    cvt_kernel<C2><<<dim3(P1/128, 2), 256>>>(dh1, dh1x, 1);
    mma_gemm<256,2,1><<<dim3(P1/128, 2), 256, SMB_GEMM>>>(dh1x, dw2x, b2, dxm, dpA, dpB);
    fold_kernel<<<C3, 256>>>(P1/128, C3, (float)P1, gg2, be2, 2);

    cvt_kernel<C3><<<dim3(PM/128, 4), 256>>>(dxm, dxmx, 2);
    mma_gemm<256,12,2><<<dim3(PT/128, 2), 256, SMB_GEMM>>>(dxmx, dwtx, bt, dy, dpA, dpB);
    fold_kernel<<<C3, 256>>>(PT/128, C3, (float)PT, ggt, bet, 3);

    final_kernel<<<(PT*C3 + 255)/256, 256>>>(out);
}

// round 9
// speedup vs baseline: 4.1405x; 1.0912x over previous
#include <cuda_runtime.h>
#include <cuda_fp16.h>
#include <cfloat>
#include <cstdint>
#include <cstddef>

#define B_  2
#define T_  16
#define NP  1024
#define KNN 16
#define TOUT 14
#define C0 6
#define C1 64
#define C2 128
#define C3 256
#define EPSV 1e-5f

#define P1 (B_*T_*NP*KNN)
#define PM (B_*T_*NP)
#define PT (B_*TOUT*NP)

// ---------------- scratch ----------------
__device__ float g_feats[(size_t)P1*C0];
__device__ float g_curs[(size_t)B_*T_*NP*3];
__device__ float g_h0[(size_t)P1*C1];
__device__ float g_h1[(size_t)P1*C2];
__device__ float g_xm[(size_t)PM*C3];
__device__ float g_y[(size_t)PT*C3];
__device__ float g_pA[(P1/128)*C3];
__device__ float g_pB[(P1/128)*C3];
__device__ float g_scale[4*256];
__device__ float g_shift[4*256];
__device__ __half g_w2x[2*256*64];
__device__ __half g_wtx[12*256*64];
__device__ __half g_h1x[(size_t)P1*C2*2];
__device__ __half g_xmx[(size_t)PM*C3*2];

#define SWZ(x) ((x) ^ (((x) >> 3) & 0x70))

__device__ __forceinline__ uint32_t smem_u32(const void* p) {
    uint32_t a;
    asm("{ .reg .u64 t; cvta.to.shared.u64 t, %1; cvt.u32.u64 %0, t; }" : "=r"(a) : "l"(p));
    return a;
}
__device__ __forceinline__ uint32_t pkh(float a, float b) {
    __half2 h = __floats2half2_rn(a, b);
    return *reinterpret_cast<uint32_t*>(&h);
}
__device__ __forceinline__ void ldm_x4(uint32_t addr, uint32_t& r0, uint32_t& r1,
                                       uint32_t& r2, uint32_t& r3) {
    asm volatile("ldmatrix.sync.aligned.m8n8.x4.shared.b16 {%0,%1,%2,%3}, [%4];"
                 : "=r"(r0), "=r"(r1), "=r"(r2), "=r"(r3) : "r"(addr));
}
__device__ __forceinline__ void mma16816h(float* d, const uint32_t* a, const uint32_t* b) {
    asm volatile("mma.sync.aligned.m16n8k16.row.col.f32.f16.f16.f32 "
        "{%0,%1,%2,%3}, {%4,%5,%6,%7}, {%8,%9}, {%0,%1,%2,%3};"
        : "+f"(d[0]), "+f"(d[1]), "+f"(d[2]), "+f"(d[3])
        : "r"(a[0]), "r"(a[1]), "r"(a[2]), "r"(a[3]), "r"(b[0]), "r"(b[1]));
}
__device__ __forceinline__ void cpasync16(uint32_t saddr, const void* g) {
    asm volatile("cp.async.cg.shared.global [%0], [%1], 16;" :: "r"(saddr), "l"(g));
}
#define CP_COMMIT() asm volatile("cp.async.commit_group;" ::: "memory")
#define CP_WAIT(n)  asm volatile("cp.async.wait_group %0;" :: "n"(n) : "memory")

__device__ __forceinline__ float shfl_sum3(float v) {
    v += __shfl_xor_sync(0xffffffffu, v, 4);
    v += __shfl_xor_sync(0xffffffffu, v, 8);
    v += __shfl_xor_sync(0xffffffffu, v, 16);
    return v;
}
__device__ __forceinline__ float shfl_max3(float v) {
    v = fmaxf(v, __shfl_xor_sync(0xffffffffu, v, 4));
    v = fmaxf(v, __shfl_xor_sync(0xffffffffu, v, 8));
    v = fmaxf(v, __shfl_xor_sync(0xffffffffu, v, 16));
    return v;
}

// ---------------- stage 1a: trajectory pass (argmin chain only) --------------
__global__ __launch_bounds__(256) void traj_kernel(const float* __restrict__ pts)
{
    __shared__ float spts[NP*3];
    int tid = threadIdx.x;
    int w = tid >> 5, lane = tid & 31;
    int gid = blockIdx.x*8 + w;
    int b = gid >> 10, i = gid & 1023;

    float cx = pts[((size_t)(b*T_)*NP + i)*3 + 0];
    float cy = pts[((size_t)(b*T_)*NP + i)*3 + 1];
    float cz = pts[((size_t)(b*T_)*NP + i)*3 + 2];

    for (int t = 0; t < T_; t++) {
        const float* pt = pts + (size_t)(b*T_ + t)*NP*3;
        for (int e = tid; e < NP*3; e += 256) spts[e] = pt[e];
        __syncthreads();
        if (lane == 0) {
            float* c = g_curs + ((size_t)(b*T_ + t)*NP + i)*3;
            c[0] = cx; c[1] = cy; c[2] = cz;
        }
        float bv = FLT_MAX; int bj = NP;
        #pragma unroll
        for (int m = 0; m < NP/32; m++) {
            int j = lane + m*32;
            float dx = cx - spts[j*3+0];
            float dy = cy - spts[j*3+1];
            float dz = cz - spts[j*3+2];
            float v = dx*dx + dy*dy + dz*dz;
            if (v < bv) { bv = v; bj = j; }
        }
        #pragma unroll
        for (int off = 16; off; off >>= 1) {
            float ov = __shfl_xor_sync(0xffffffffu, bv, off);
            int   oj = __shfl_xor_sync(0xffffffffu, bj, off);
            if (ov < bv || (ov == bv && oj < bj)) { bv = ov; bj = oj; }
        }
        cx = spts[bj*3+0]; cy = spts[bj*3+1]; cz = spts[bj*3+2];
        __syncthreads();
    }
}

// ---------------- stage 1b: parallel top-16, incremental segment minima ------
// slot(j) = (j&31)*33 + (j>>5). Segment s = [32s, 32s+32).
#define TK_PAD 33
__global__ __launch_bounds__(256) void topk_kernel(const float* __restrict__ pts)
{
    extern __shared__ float sm[];
    float* spts = sm;                                // 3072
    float* d2a  = sm + 3072;                          // 8 * 33*32 = 8448
    int*   selw = (int*)(sm + 3072 + 8*TK_PAD*32);    // 8*16

    int tid = threadIdx.x;
    int w = tid >> 5, lane = tid & 31;
    int bt  = blockIdx.x >> 7;
    int grp = blockIdx.x & 127;
    int b = bt >> 4, t = bt & 15;
    int n = grp*8 + w;

    const float* pt = pts + (size_t)(b*T_ + t)*NP*3;
    const float* pp = pts + (size_t)(b*T_ + (t == 0 ? 0 : t-1))*NP*3;
    for (int e = tid; e < NP*3; e += 256) spts[e] = pt[e];
    __syncthreads();

    const float* cq = g_curs + ((size_t)bt*NP + n)*3;
    float cx = cq[0], cy = cq[1], cz = cq[2];
    const float* aq = g_curs + ((size_t)(b*T_ + 1)*NP + n)*3;
    float ax = aq[0], ay = aq[1], az = aq[2];

    float* dw = d2a + w*(TK_PAD*32);
    // distances: lane l handles j = l + 32m  ->  slot l*33 + m (conflict-free)
    #pragma unroll
    for (int m = 0; m < 32; m++) {
        int j = lane + 32*m;
        float dx = cx - spts[j*3+0];
        float dy = cy - spts[j*3+1];
        float dz = cz - spts[j*3+2];
        dw[lane*TK_PAD + m] = dx*dx + dy*dy + dz*dz;
    }
    __syncwarp();
    // segment minima: lane s scans j = 32s + m at slot m*33 + s (conflict-free)
    float segV = FLT_MAX; int segJ = NP;
    #pragma unroll
    for (int m = 0; m < 32; m++) {
        float v = dw[m*TK_PAD + lane];
        if (v < segV) { segV = v; segJ = lane*32 + m; }
    }

    for (int k = 0; k < KNN; k++) {
        // global min over 32 segment minima
        float gv = segV; int gj = segJ;
        #pragma unroll
        for (int off = 16; off; off >>= 1) {
            float ov = __shfl_xor_sync(0xffffffffu, gv, off);
            int   oj = __shfl_xor_sync(0xffffffffu, gj, off);
            if (ov < gv || (ov == gv && oj < gj)) { gv = ov; gj = oj; }
        }
        if (lane == 0) selw[w*KNN + k] = gj;
        int s = gj >> 5;
        if (lane == (gj & 31)) dw[(gj & 31)*TK_PAD + s] = FLT_MAX;
        __syncwarp();
        // cooperative rescan of segment s: lane m -> slot m*33+s (conflict-free)
        float v = dw[lane*TK_PAD + s];
        int j = 32*s + lane;
        #pragma unroll
        for (int off = 16; off; off >>= 1) {
            float ov = __shfl_xor_sync(0xffffffffu, v, off);
            int   oj = __shfl_xor_sync(0xffffffffu, j, off);
            if (ov < v || (ov == v && oj < j)) { v = ov; j = oj; }
        }
        if (lane == s) { segV = v; segJ = j; }
    }
    __syncwarp();

    size_t basef = ((size_t)bt*NP + n) * KNN;
    if (lane < KNN) {
        int sj = selw[w*KNN + lane];
        float* dst = g_feats + (basef + lane)*6;
        dst[0] = pp[sj*3+0]; dst[1] = pp[sj*3+1]; dst[2] = pp[sj*3+2];
        dst[3] = spts[sj*3+0] - ax; dst[4] = spts[sj*3+1] - ay; dst[5] = spts[sj*3+2] - az;
    }
}

// ---------------- layer 0 (6 -> 64) with per-block BN partials ----------------
__global__ __launch_bounds__(256) void mlp0_kernel(const float* __restrict__ w,
                                                   const float* __restrict__ bias)
{
    __shared__ float sf[64][C0];
    __shared__ float sw[C1*C0];
    __shared__ float sb[C1];
    __shared__ float2 red[4][C1];
    int tid = threadIdx.y*64 + threadIdx.x;
    int p0 = blockIdx.x * 64;
    for (int e = tid; e < 64*C0; e += 256) sf[e/C0][e%C0] = g_feats[(size_t)p0*C0 + e];
    for (int e = tid; e < C1*C0; e += 256) sw[e] = w[e];
    if (tid < C1) sb[tid] = bias[tid];
    __syncthreads();
    int c = threadIdx.x;
    float lw[C0];
    #pragma unroll
    for (int j = 0; j < C0; j++) lw[j] = sw[c*C0+j];
    float bsv = sb[c];
    float lsum = 0.f, lsq = 0.f;
    for (int pi = threadIdx.y; pi < 64; pi += 4) {
        float acc = bsv;
        #pragma unroll
        for (int j = 0; j < C0; j++) acc += sf[pi][j]*lw[j];
        g_h0[(size_t)(p0+pi)*C1 + c] = acc;
        lsum += acc; lsq += acc*acc;
    }
    red[threadIdx.y][c] = make_float2(lsum, lsq);
    __syncthreads();
    if (threadIdx.y == 0) {
        float s = 0.f, q = 0.f;
        #pragma unroll
        for (int r = 0; r < 4; r++) { s += red[r][c].x; q += red[r][c].y; }
        g_pA[blockIdx.x*C1 + c] = s;
        g_pB[blockIdx.x*C1 + c] = q;
    }
}

// ---------------- fold BN stats (one block per channel) ----------------
__global__ void fold_kernel(int nblk, int C, float cnt,
                            const float* __restrict__ g, const float* __restrict__ be,
                            int slot)
{
    int c = blockIdx.x;
    double s = 0.0, q = 0.0;
    for (int r = threadIdx.x; r < nblk; r += 256) {
        s += (double)g_pA[r*C + c];
        q += (double)g_pB[r*C + c];
    }
    __shared__ double sh[512];
    sh[threadIdx.x] = s; sh[256 + threadIdx.x] = q;
    __syncthreads();
    for (int o = 128; o; o >>= 1) {
        if (threadIdx.x < o) {
            sh[threadIdx.x] += sh[threadIdx.x + o];
            sh[256 + threadIdx.x] += sh[256 + threadIdx.x + o];
        }
        __syncthreads();
    }
    if (threadIdx.x == 0) {
        double m = sh[0] / (double)cnt;
        double v = sh[256] / (double)cnt - m*m;
        float sc = g[c] * rsqrtf((float)v + EPSV);
        g_scale[slot*256 + c] = sc;
        g_shift[slot*256 + c] = be[c] - (float)m * sc;
    }
}

// ---------------- weight prep ----------------
__global__ void prepw_kernel(const float* __restrict__ W, int N, int Cin,
                             __half* __restrict__ dst)
{
    int i = blockIdx.x*256 + threadIdx.x;
    if (i >= N*Cin) return;
    int n = i / Cin, c = i % Cin;
    int chunk = c >> 6, k = c & 63;
    int off = SWZ(n*128 + k*2) >> 1;
    dst[(size_t)chunk*(N*64) + off] = __float2half_rn(W[i]);
}

__global__ void prepwt_kernel(const float* __restrict__ wt)
{
    int i = blockIdx.x*256 + threadIdx.x;
    if (i >= C3*C3*3) return;
    int dt = i % 3;
    int c  = (i / 3) % C3;
    int o  = i / (3*C3);
    int chunk = dt*4 + (c >> 6);
    int k = c & 63;
    int off = SWZ(o*128 + k*2) >> 1;
    g_wtx[(size_t)chunk*(C3*64) + off] = __float2half_rn(wt[i]);
}

// ---------------- activation convert: affine+relu -> split fp16 tiles --------
template<int CIN>
__global__ __launch_bounds__(256) void cvt_kernel(const float* __restrict__ src,
                                                  __half* __restrict__ dst,
                                                  int affSlot)
{
    __shared__ float sS[64], sC[64];
    int tid = threadIdx.x;
    if (tid < 64) {
        sS[tid] = g_scale[affSlot*256 + blockIdx.y*64 + tid];
        sC[tid] = g_shift[affSlot*256 + blockIdx.y*64 + tid];
    }
    __syncthreads();
    char* out = (char*)dst + ((size_t)blockIdx.x*gridDim.y + blockIdx.y)*32768;
    const float* Ab = src + (size_t)blockIdx.x*128*CIN + blockIdx.y*64;
    #pragma unroll
    for (int i = 0; i < 8; i++) {
        int f = tid + i*256;
        int row = f >> 4;
        int k = (f & 15) * 4;
        float4 v = *(const float4*)(Ab + (size_t)row*CIN + k);
        v.x = fmaxf(fmaf(v.x, sS[k+0], sC[k+0]), 0.f);
        v.y = fmaxf(fmaf(v.y, sS[k+1], sC[k+1]), 0.f);
        v.z = fmaxf(fmaf(v.z, sS[k+2], sC[k+2]), 0.f);
        v.w = fmaxf(fmaf(v.w, sS[k+3], sC[k+3]), 0.f);
        float h0 = __half2float(__float2half_rn(v.x));
        float h1 = __half2float(__float2half_rn(v.y));
        float h2 = __half2float(__float2half_rn(v.z));
        float h3 = __half2float(__float2half_rn(v.w));
        uint32_t off = SWZ((uint32_t)(row*128 + k*2));
        *(uint2*)(out + off)         = make_uint2(pkh(v.x, v.y), pkh(v.z, v.w));
        *(uint2*)(out + 16384 + off) = make_uint2(pkh(v.x - h0, v.y - h1), pkh(v.z - h2, v.w - h3));
    }
}

// ---------------- gemm1: 64->128, 4 row-tiles per block, pipelined -----------
#define OFFG_W    0
#define OFFG_RAW  16384
#define OFFG_AHI  49152
#define OFFG_ALO  65536
#define OFFG_SS   81920
#define OFFG_SC   82176
#define OFFG_BIAS 82432
#define OFFG_PS   82944
#define OFFG_PQ   83968
#define SMBG1     84992
#define G1_TILES  4

__global__ __launch_bounds__(256, 2) void mma_gemm1(
    const float* __restrict__ A, const float* __restrict__ W,
    const float* __restrict__ bias,
    float* __restrict__ out, float* __restrict__ pA, float* __restrict__ pB)
{
    extern __shared__ __align__(1024) char smem[];
    const int tid = threadIdx.x;
    const int wid = tid >> 5, lane = tid & 31;
    const int warpRow = wid & 1, warpCol = wid >> 1;
    const uint32_t sb32 = smem_u32(smem);

    float* sS = (float*)(smem + OFFG_SS);
    float* sC = (float*)(smem + OFFG_SC);
    float* sbias = (float*)(smem + OFFG_BIAS);
    if (tid < 64) { sS[tid] = g_scale[tid]; sC[tid] = g_shift[tid]; }
    if (tid < 128) sbias[tid] = bias[tid];
    for (int i = tid; i < 128*64; i += 256) {
        int n = i >> 6, c = i & 63;
        *(__half*)(smem + OFFG_W + SWZ(n*128 + c*2)) = __float2half_rn(W[i]);
    }
    {
        const char* Ab = (const char*)(A + (size_t)(blockIdx.x*G1_TILES)*128*64);
        #pragma unroll
        for (int i = 0; i < 8; i++) {
            int o = (tid + i*256) * 16;
            cpasync16(sb32 + OFFG_RAW + o, Ab + o);
        }
        CP_COMMIT();
    }
    __syncthreads();

    for (int tile = 0; tile < G1_TILES; tile++) {
        int rowBase = (blockIdx.x*G1_TILES + tile)*128;
        CP_WAIT(0);
        __syncthreads();
        #pragma unroll
        for (int i = 0; i < 8; i++) {
            int f = tid + i*256;
            int row = f >> 4;
            int k = (f & 15) * 4;
            float4 v = *(const float4*)(smem + OFFG_RAW + (row*64 + k)*4);
            v.x = fmaxf(fmaf(v.x, sS[k+0], sC[k+0]), 0.f);
            v.y = fmaxf(fmaf(v.y, sS[k+1], sC[k+1]), 0.f);
            v.z = fmaxf(fmaf(v.z, sS[k+2], sC[k+2]), 0.f);
            v.w = fmaxf(fmaf(v.w, sS[k+3], sC[k+3]), 0.f);
            float h0 = __half2float(__float2half_rn(v.x));
            float h1 = __half2float(__float2half_rn(v.y));
            float h2 = __half2float(__float2half_rn(v.z));
            float h3 = __half2float(__float2half_rn(v.w));
            uint32_t off = SWZ((uint32_t)(row*128 + k*2));
            *(uint2*)(smem + OFFG_AHI + off) = make_uint2(pkh(v.x, v.y), pkh(v.z, v.w));
            *(uint2*)(smem + OFFG_ALO + off) = make_uint2(pkh(v.x - h0, v.y - h1), pkh(v.z - h2, v.w - h3));
        }
        __syncthreads();
        if (tile + 1 < G1_TILES) {
            const char* Ab = (const char*)(A + (size_t)(blockIdx.x*G1_TILES + tile + 1)*128*64);
            #pragma unroll
            for (int i = 0; i < 8; i++) {
                int o = (tid + i*256) * 16;
                cpasync16(sb32 + OFFG_RAW + o, Ab + o);
            }
            CP_COMMIT();
        }
        float acc[4][4][4] = {};
        #pragma unroll
        for (int ks = 0; ks < 4; ks++) {
            uint32_t bh[4][2];
            #pragma unroll
            for (int nt2 = 0; nt2 < 2; nt2++) {
                uint32_t roff = (uint32_t)((warpCol*32 + nt2*16 + ((lane>>4)<<3) + (lane&7))*128
                                           + ks*32 + (((lane>>3)&1)<<4));
                ldm_x4(sb32 + OFFG_W + SWZ(roff), bh[nt2*2][0], bh[nt2*2][1], bh[nt2*2+1][0], bh[nt2*2+1][1]);
            }
            #pragma unroll
            for (int mt = 0; mt < 4; mt++) {
                uint32_t roff = (uint32_t)((warpRow*64 + mt*16 + (lane&15))*128
                                           + ks*32 + ((lane>>4)<<4));
                uint32_t ah[4], al[4];
                ldm_x4(sb32 + OFFG_AHI + SWZ(roff), ah[0], ah[1], ah[2], ah[3]);
                ldm_x4(sb32 + OFFG_ALO + SWZ(roff), al[0], al[1], al[2], al[3]);
                #pragma unroll
                for (int nt = 0; nt < 4; nt++) mma16816h(acc[mt][nt], ah, bh[nt]);
                #pragma unroll
                for (int nt = 0; nt < 4; nt++) mma16816h(acc[mt][nt], al, bh[nt]);
            }
        }
        #pragma unroll
        for (int nt = 0; nt < 4; nt++) {
            int cl = warpCol*32 + nt*8 + (lane&3)*2;
            float b0 = sbias[cl], b1 = sbias[cl+1];
            #pragma unroll
            for (int mt = 0; mt < 4; mt++) {
                acc[mt][nt][0] += b0; acc[mt][nt][1] += b1;
                acc[mt][nt][2] += b0; acc[mt][nt][3] += b1;
            }
        }
        float* ps = (float*)(smem + OFFG_PS);
        float* pq = (float*)(smem + OFFG_PQ);
        #pragma unroll
        for (int nt = 0; nt < 4; nt++) {
            float s0 = 0.f, s1 = 0.f, q0 = 0.f, q1 = 0.f;
            #pragma unroll
            for (int mt = 0; mt < 4; mt++) {
                float c0 = acc[mt][nt][0], c1 = acc[mt][nt][1];
                float c2 = acc[mt][nt][2], c3 = acc[mt][nt][3];
                s0 += c0 + c2; s1 += c1 + c3;
                q0 += c0*c0 + c2*c2; q1 += c1*c1 + c3*c3;
            }
            s0 = shfl_sum3(s0); s1 = shfl_sum3(s1);
            q0 = shfl_sum3(q0); q1 = shfl_sum3(q1);
            if (lane < 4) {
                int cl = warpCol*32 + nt*8 + lane*2;
                ps[warpRow*128 + cl] = s0; ps[warpRow*128 + cl + 1] = s1;
                pq[warpRow*128 + cl] = q0; pq[warpRow*128 + cl + 1] = q1;
            }
        }
        #pragma unroll
        for (int mt = 0; mt < 4; mt++) {
            int r0 = rowBase + warpRow*64 + mt*16 + (lane >> 2);
            #pragma unroll
            for (int nt = 0; nt < 4; nt++) {
                int cl = warpCol*32 + nt*8 + (lane&3)*2;
                *(float2*)&out[(size_t)r0*C2 + cl]     = make_float2(acc[mt][nt][0], acc[mt][nt][1]);
                *(float2*)&out[(size_t)(r0+8)*C2 + cl] = make_float2(acc[mt][nt][2], acc[mt][nt][3]);
            }
        }
        __syncthreads();
        if (tid < 128) {
            pA[(size_t)(blockIdx.x*G1_TILES + tile)*C2 + tid] = ps[tid] + ps[128 + tid];
            pB[(size_t)(blockIdx.x*G1_TILES + tile)*C2 + tid] = pq[tid] + pq[128 + tid];
        }
    }
}

// ---------------- general GEMM: A pre-converted tiles, W fp16 plane ----------
// Grid: (colblocks, rowblocks) so the 2 colblocks of one row-tile are launch-
// adjacent and the second A-tile read hits L2.
#define OFF_A0   0
#define OFF_A1   32768
#define OFF_W0   65536
#define OFF_W1   81920
#define OFF_BIAS 98304
#define OFF_PS   98816
#define OFF_PQ   99840
#define SMB_GEMM 100864

template<int COUT, int NCHUNK, int MODE>
__global__ __launch_bounds__(256, 2) void mma_gemm(
    const __half* __restrict__ Ax, const __half* __restrict__ Wx,
    const float* __restrict__ bias,
    float* __restrict__ out, float* __restrict__ pA, float* __restrict__ pB)
{
    extern __shared__ __align__(1024) char smem[];
    const int tid = threadIdx.x;
    const int wid = tid >> 5, lane = tid & 31;
    const int warpRow = wid & 1, warpCol = wid >> 1;
    const int rowBlk  = blockIdx.y;
    const int rowBase = rowBlk * 128;
    const int colBase = blockIdx.x * 128;
    const uint32_t sb32 = smem_u32(smem);

    float* sbias = (float*)(smem + OFF_BIAS);
    if (tid < 128) sbias[tid] = bias[colBase + tid];

    int bb = 0, to = 0, n0 = 0;
    if (MODE == 2) { bb = rowBase/(TOUT*NP); to = (rowBase/NP) % TOUT; n0 = rowBase % NP; }

    auto a_tile = [&](int chunk) -> size_t {
        if (MODE == 2) {
            int dt = chunk >> 2, kc = chunk & 3;
            int rb = (bb*T_ + to + dt)*(NP/128) + (n0 >> 7);
            return ((size_t)rb*4 + kc)*32768;
        }
        return ((size_t)rowBlk*NCHUNK + chunk)*32768;
    };
    auto issue = [&](int chunk) {
        uint32_t abase = (chunk & 1) ? OFF_A1 : OFF_A0;
        uint32_t wbase = (chunk & 1) ? OFF_W1 : OFF_W0;
        const char* As = (const char*)Ax + a_tile(chunk);
        #pragma unroll
        for (int i = 0; i < 8; i++) {
            int o = (tid + i*256) * 16;
            cpasync16(sb32 + abase + o, As + o);
        }
        const char* Wp = (const char*)(Wx + (size_t)chunk*((size_t)COUT*64) + (size_t)colBase*64);
        #pragma unroll
        for (int i = 0; i < 4; i++) {
            int o = (tid + i*256) * 16;
            cpasync16(sb32 + wbase + o, Wp + o);
        }
        CP_COMMIT();
    };

    float acc[4][4][4] = {};

    issue(0);
    if (NCHUNK > 1) issue(1);

    for (int chunk = 0; chunk < NCHUNK; chunk++) {
        if (chunk + 1 < NCHUNK) { CP_WAIT(1); } else { CP_WAIT(0); }
        __syncthreads();
        uint32_t abase = (chunk & 1) ? OFF_A1 : OFF_A0;
        uint32_t wbase = (chunk & 1) ? OFF_W1 : OFF_W0;
        #pragma unroll
        for (int ks = 0; ks < 4; ks++) {
            uint32_t bh[4][2];
            #pragma unroll
            for (int nt2 = 0; nt2 < 2; nt2++) {
                uint32_t roff = (uint32_t)((warpCol*32 + nt2*16 + ((lane>>4)<<3) + (lane&7))*128
                                           + ks*32 + (((lane>>3)&1)<<4));
                ldm_x4(sb32 + wbase + SWZ(roff), bh[nt2*2][0], bh[nt2*2][1], bh[nt2*2+1][0], bh[nt2*2+1][1]);
            }
            #pragma unroll
            for (int mt = 0; mt < 4; mt++) {
                uint32_t roff = (uint32_t)((warpRow*64 + mt*16 + (lane&15))*128
                                           + ks*32 + ((lane>>4)<<4));
                uint32_t ah[4], al[4];
                ldm_x4(sb32 + abase + SWZ(roff), ah[0], ah[1], ah[2], ah[3]);
                ldm_x4(sb32 + abase + 16384 + SWZ(roff), al[0], al[1], al[2], al[3]);
                #pragma unroll
                for (int nt = 0; nt < 4; nt++) mma16816h(acc[mt][nt], ah, bh[nt]);
                #pragma unroll
                for (int nt = 0; nt < 4; nt++) mma16816h(acc[mt][nt], al, bh[nt]);
            }
        }
        __syncthreads();
        if (chunk + 2 < NCHUNK) issue(chunk + 2);
    }

    // -------- epilogue --------
    #pragma unroll
    for (int nt = 0; nt < 4; nt++) {
        int cl = warpCol*32 + nt*8 + (lane&3)*2;
        float b0 = sbias[cl], b1 = sbias[cl+1];
        #pragma unroll
        for (int mt = 0; mt < 4; mt++) {
            acc[mt][nt][0] += b0; acc[mt][nt][1] += b1;
            acc[mt][nt][2] += b0; acc[mt][nt][3] += b1;
        }
    }
    float* ps = (float*)(smem + OFF_PS);
    float* pq = (float*)(smem + OFF_PQ);
    #pragma unroll
    for (int nt = 0; nt < 4; nt++) {
        float s0 = 0.f, s1 = 0.f, q0 = 0.f, q1 = 0.f;
        #pragma unroll
        for (int mt = 0; mt < 4; mt++) {
            float c0 = acc[mt][nt][0], c1 = acc[mt][nt][1];
            float c2 = acc[mt][nt][2], c3 = acc[mt][nt][3];
            s0 += c0 + c2; s1 += c1 + c3;
            q0 += c0*c0 + c2*c2; q1 += c1*c1 + c3*c3;
        }
        s0 = shfl_sum3(s0); s1 = shfl_sum3(s1);
        q0 = shfl_sum3(q0); q1 = shfl_sum3(q1);
        if (lane < 4) {
            int cl = warpCol*32 + nt*8 + lane*2;
            ps[warpRow*128 + cl] = s0; ps[warpRow*128 + cl + 1] = s1;
            pq[warpRow*128 + cl] = q0; pq[warpRow*128 + cl + 1] = q1;
        }
    }
    if (MODE == 1) {
        #pragma unroll
        for (int mt = 0; mt < 4; mt++) {
            int grow = (rowBase >> 4) + warpRow*4 + mt;
            #pragma unroll
            for (int nt = 0; nt < 4; nt++) {
                float m0 = shfl_max3(fmaxf(acc[mt][nt][0], acc[mt][nt][2]));
                float m1 = shfl_max3(fmaxf(acc[mt][nt][1], acc[mt][nt][3]));
                if (lane < 4) {
                    int cl = colBase + warpCol*32 + nt*8 + lane*2;
                    *(float2*)&out[(size_t)grow*COUT + cl] = make_float2(m0, m1);
                }
            }
        }
    } else {
        float* tile = (float*)smem;
        __syncthreads();
        #pragma unroll
        for (int mt = 0; mt < 4; mt++) {
            int r0 = warpRow*64 + mt*16 + (lane >> 2);
            #pragma unroll
            for (int nt = 0; nt < 4; nt++) {
                int cl = warpCol*32 + nt*8 + (lane&3)*2;
                *(float2*)&tile[(r0)*132 + cl]   = make_float2(acc[mt][nt][0], acc[mt][nt][1]);
                *(float2*)&tile[(r0+8)*132 + cl] = make_float2(acc[mt][nt][2], acc[mt][nt][3]);
            }
        }
        __syncthreads();
        int r = tid >> 1, half = (tid & 1)*64;
        const float* src = tile + r*132 + half;
        float* dst = out + (size_t)(rowBase + r)*COUT + colBase + half;
        #pragma unroll
        for (int i = 0; i < 16; i++)
            *(float4*)(dst + i*4) = *(const float4*)(src + i*4);
    }
    __syncthreads();
    if (tid < 128) {
        pA[(size_t)rowBlk*COUT + colBase + tid] = ps[tid] + ps[128 + tid];
        pB[(size_t)rowBlk*COUT + colBase + tid] = pq[tid] + pq[128 + tid];
    }
}

// ---------------- final BN + relu -> output ----------------
__global__ void final_kernel(float* __restrict__ out)
{
    int i = blockIdx.x*blockDim.x + threadIdx.x;
    if (i < PT*C3) {
        int c = i & 255;
        out[i] = fmaxf(g_y[i]*g_scale[3*256 + c] + g_shift[3*256 + c], 0.f);
    }
}

// ---------------- launch ----------------
extern "C" void kernel_launch(void* const* d_in, const int* in_sizes, int n_in,
                              void* d_out, int out_size)
{
    (void)in_sizes; (void)n_in; (void)out_size;
    const float* pts = (const float*)d_in[0];
    const float* w0  = (const float*)d_in[1];
    const float* b0  = (const float*)d_in[2];
    const float* gg0 = (const float*)d_in[3];
    const float* be0 = (const float*)d_in[4];
    const float* w1  = (const float*)d_in[5];
    const float* b1  = (const float*)d_in[6];
    const float* gg1 = (const float*)d_in[7];
    const float* be1 = (const float*)d_in[8];
    const float* w2  = (const float*)d_in[9];
    const float* b2  = (const float*)d_in[10];
    const float* gg2 = (const float*)d_in[11];
    const float* be2 = (const float*)d_in[12];
    const float* wt  = (const float*)d_in[13];
    const float* bt  = (const float*)d_in[14];
    const float* ggt = (const float*)d_in[15];
    const float* bet = (const float*)d_in[16];
    float* out = (float*)d_out;

    float *dh0 = nullptr, *dh1 = nullptr, *dxm = nullptr, *dy = nullptr;
    float *dpA = nullptr, *dpB = nullptr;
    __half *dw2x = nullptr, *dwtx = nullptr, *dh1x = nullptr, *dxmx = nullptr;
    cudaGetSymbolAddress((void**)&dh0, g_h0);
    cudaGetSymbolAddress((void**)&dh1, g_h1);
    cudaGetSymbolAddress((void**)&dxm, g_xm);
    cudaGetSymbolAddress((void**)&dy, g_y);
    cudaGetSymbolAddress((void**)&dpA, g_pA);
    cudaGetSymbolAddress((void**)&dpB, g_pB);
    cudaGetSymbolAddress((void**)&dw2x, g_w2x);
    cudaGetSymbolAddress((void**)&dwtx, g_wtx);
    cudaGetSymbolAddress((void**)&dh1x, g_h1x);
    cudaGetSymbolAddress((void**)&dxmx, g_xmx);

    const int SMB_TOPK = (3072 + 8*TK_PAD*32)*4 + 8*KNN*4;
    static bool attr_set = false;
    if (!attr_set) {
        cudaFuncSetAttribute(topk_kernel,       cudaFuncAttributeMaxDynamicSharedMemorySize, SMB_TOPK);
        cudaFuncSetAttribute(mma_gemm1,         cudaFuncAttributeMaxDynamicSharedMemorySize, SMBG1);
        cudaFuncSetAttribute(mma_gemm<256,2,1>, cudaFuncAttributeMaxDynamicSharedMemorySize, SMB_GEMM);
        cudaFuncSetAttribute(mma_gemm<256,12,2>,cudaFuncAttributeMaxDynamicSharedMemorySize, SMB_GEMM);
        attr_set = true;
    }

    prepw_kernel<<<(C3*C2 + 255)/256, 256>>>(w2, C3, C2, dw2x);
    prepwt_kernel<<<(C3*C3*3 + 255)/256, 256>>>(wt);
    traj_kernel<<<B_*NP/8, 256>>>(pts);
    topk_kernel<<<B_*T_*128, 256, SMB_TOPK>>>(pts);   // launch #4: profiled

    mlp0_kernel<<<P1/64, dim3(64,4)>>>(w0, b0);
    fold_kernel<<<C1, 256>>>(P1/64, C1, (float)P1, gg0, be0, 0);

    mma_gemm1<<<P1/128/G1_TILES, 256, SMBG1>>>(dh0, w1, b1, dh1, dpA, dpB);
    fold_kernel<<<C2, 256>>>(P1/128, C2, (float)P1, gg1, be1, 1);

    cvt_kernel<C2><<<dim3(P1/128, 2), 256>>>(dh1, dh1x, 1);
    mma_gemm<256,2,1><<<dim3(2, P1/128), 256, SMB_GEMM>>>(dh1x, dw2x, b2, dxm, dpA, dpB);
    fold_kernel<<<C3, 256>>>(P1/128, C3, (float)P1, gg2, be2, 2);

    cvt_kernel<C3><<<dim3(PM/128, 4), 256>>>(dxm, dxmx, 2);
    mma_gemm<256,12,2><<<dim3(2, PT/128), 256, SMB_GEMM>>>(dxmx, dwtx, bt, dy, dpA, dpB);
    fold_kernel<<<C3, 256>>>(PT/128, C3, (float)PT, ggt, bet, 3);

    final_kernel<<<(PT*C3 + 255)/256, 256>>>(out);
}